// round 1
// baseline (speedup 1.0000x reference)
#include <cuda_runtime.h>
#include <math.h>

#define Bv 64
#define Cv 21
#define Pv 96
#define Dv 256
#define Rv 32
#define Hv 64
#define BPv (Bv*Pv)
#define PDv (Pv*Dv)

// Precomputed weight transforms (device globals: allocation-free scratch)
__device__ float g_WdT[Rv*Dv];    // [r][d] = ln_w[d]*Wd[d][r]
__device__ float g_dn1T[Hv*Dv];   // [j][d] = dn1_w[d][j]
__device__ float g_SW[Rv];        // sum_d ln_w[d]*Wd[d][r]
__device__ float g_LB[Rv];        // sum_d ln_b[d]*Wd[d][r] + bd[r]
__device__ float g_logits[Dv];    // channel_logits (shared by all bp)

static __device__ __forceinline__ float geluf(float x) {
    return 0.5f * x * (1.0f + erff(x * 0.70710678118654752f));
}
static __device__ __forceinline__ float sigm(float x) {
    return 1.0f / (1.0f + expf(-x));
}

// Blackwell packed f32x2 helpers
static __device__ __forceinline__ unsigned long long pk2(float a, float b) {
    unsigned long long r;
    asm("mov.b64 %0, {%1,%2};" : "=l"(r) : "f"(a), "f"(b));
    return r;
}
static __device__ __forceinline__ void ffma2(unsigned long long& d,
                                             unsigned long long a,
                                             unsigned long long b) {
    asm("fma.rn.f32x2 %0, %1, %2, %3;" : "=l"(d) : "l"(a), "l"(b), "l"(d));
}
static __device__ __forceinline__ float upksum(unsigned long long v) {
    float lo, hi;
    asm("mov.b64 {%0,%1}, %2;" : "=f"(lo), "=f"(hi) : "l"(v));
    return lo + hi;
}

// ---------------------------------------------------------------------------
// Prep kernel: 98 blocks x 256 threads. Builds W' transpose, dn1 transpose,
// SW/LB folds, and the (bp-invariant) channel logits.
// ---------------------------------------------------------------------------
__global__ void prep_kernel(const float* __restrict__ ln_w, const float* __restrict__ ln_b,
                            const float* __restrict__ Wd,   const float* __restrict__ bd,
                            const float* __restrict__ cn1_w, const float* __restrict__ cn1_b,
                            const float* __restrict__ cn2_w, const float* __restrict__ cn2_b,
                            const float* __restrict__ dn1_w) {
    int bi = blockIdx.x, tid = threadIdx.x;
    if (bi < 32) {
        // W'T row bi
        g_WdT[bi * Dv + tid] = ln_w[tid] * Wd[tid * Rv + bi];
    } else if (bi < 96) {
        int j = bi - 32;
        g_dn1T[j * Dv + tid] = dn1_w[tid * Hv + j];
    } else if (bi == 96) {
        __shared__ float ssw[8][32], slb[8][32];
        int r = tid & 31, seg = tid >> 5;
        float sw = 0.f, lb = 0.f;
        for (int dd = 0; dd < 32; dd++) {
            int d = seg * 32 + dd;
            float wv = Wd[d * Rv + r];
            sw += ln_w[d] * wv;
            lb += ln_b[d] * wv;
        }
        ssw[seg][r] = sw; slb[seg][r] = lb;
        __syncthreads();
        if (tid < 32) {
            float a = 0.f, b2 = 0.f;
            #pragma unroll
            for (int s = 0; s < 8; s++) { a += ssw[s][tid]; b2 += slb[s][tid]; }
            g_SW[tid] = a;
            g_LB[tid] = b2 + bd[tid];
        }
    } else {
        // channel logits: gelu(lc*cn1_w + cn1_b) @ cn2_w + cn2_b
        __shared__ float hid[Hv];
        const float lc = logf(21.0f) / logf(1000.0f);
        if (tid < Hv) hid[tid] = geluf(lc * cn1_w[tid] + cn1_b[tid]);
        __syncthreads();
        float acc = cn2_b[tid];
        for (int j = 0; j < Hv; j++) acc += hid[j] * cn2_w[j * Dv + tid];
        g_logits[tid] = acc;
    }
}

// ---------------------------------------------------------------------------
// Main kernel: one CTA per (b,p). 256 threads, 8 warps.
// ---------------------------------------------------------------------------
__global__ __launch_bounds__(256, 2) void hydra_kernel(
    const float* __restrict__ x,
    const float* __restrict__ Wq, const float* __restrict__ Wk,
    const float* __restrict__ Wv, const float* __restrict__ Wg,
    const float* __restrict__ bg,
    const float* __restrict__ Wu, const float* __restrict__ bu,
    const float* __restrict__ dn1_b,
    const float* __restrict__ dn2_w, const float* __restrict__ dn2_b,
    const float* __restrict__ eps_p,
    float* __restrict__ out)
{
    __shared__ float h_s[Cv * Dv];       // raw (transposed) x tile
    __shared__ float hl_s[Cv * Rv];      // h_low
    __shared__ float A_s[Cv * Rv];       // qn * gate (gf folded later)
    __shared__ float cv_s[Dv];           // channel variance (ddof=1)
    __shared__ float mu_s[Cv], rs_s[Cv];
    __shared__ float gf_s[8 * Rv];       // per-warp partial global_feat
    __shared__ float hid2_s[Hv];         // data-MLP hidden

    const int tid = threadIdx.x;
    const int lane = tid & 31;
    const int w = tid >> 5;
    const int bp = blockIdx.x;
    const int b = bp / Pv, p = bp % Pv;
    const int base = b * Cv * PDv + p * Dv + tid;   // < 2^25, int is safe

    // ---- phase 1: load tile + per-column (channel-dim) stats --------------
    float s1 = 0.f, s2 = 0.f;
    #pragma unroll
    for (int c = 0; c < Cv; c++) {
        float v = x[base + c * PDv];
        h_s[c * Dv + tid] = v;
        s1 += v; s2 += v * v;
    }
    cv_s[tid] = (s2 - s1 * s1 * (1.0f / 21.0f)) * (1.0f / 20.0f);
    __syncthreads();

    // ---- phase 2: LayerNorm row stats (warp w owns rows w, w+8, w+16) ----
    #pragma unroll
    for (int ci = 0; ci < 3; ci++) {
        int c = w + 8 * ci;
        if (c < Cv) {   // warp-uniform
            float s = 0.f, ss = 0.f;
            #pragma unroll
            for (int k = 0; k < 8; k++) {
                float v = h_s[c * Dv + lane + 32 * k];
                s += v; ss += v * v;
            }
            #pragma unroll
            for (int o = 16; o > 0; o >>= 1) {
                s  += __shfl_xor_sync(0xffffffffu, s, o);
                ss += __shfl_xor_sync(0xffffffffu, ss, o);
            }
            if (lane == 0) {
                float mu = s * (1.0f / 256.0f);
                float var = ss * (1.0f / 256.0f) - mu * mu;
                mu_s[c] = mu;
                rs_s[c] = rsqrtf(var + 1e-5f);
            }
        }
    }
    __syncthreads();   // mu/rs + (phase1 already) ready

    // ---- phase 3: data-MLP hidden (8 j per warp) --------------------------
    #pragma unroll
    for (int jj = 0; jj < 8; jj++) {
        int j = w * 8 + jj;
        float part = 0.f;
        #pragma unroll
        for (int k = 0; k < 8; k++) {
            int d = lane + 32 * k;
            part += cv_s[d] * __ldg(&g_dn1T[j * Dv + d]);
        }
        #pragma unroll
        for (int o = 16; o > 0; o >>= 1)
            part += __shfl_xor_sync(0xffffffffu, part, o);
        if (lane == 0) hid2_s[j] = geluf(part + __ldg(&dn1_b[j]));
    }

    // ---- phase 4: h_low = LN-folded GEMM  [21,256]@[256,32] ---------------
    {
        const int r = lane;
        const int c0 = w, c1 = w + 8;
        const int c2 = (w + 16 < Cv) ? (w + 16) : (Cv - 1);   // clamp, guard store
        unsigned long long a00 = pk2(0.f, 0.f), a01 = a00, a10 = a00,
                           a11 = a00, a20 = a00, a21 = a00;
        const float4* wrow = reinterpret_cast<const float4*>(g_WdT + r * Dv);
        const float4* h0 = reinterpret_cast<const float4*>(h_s + c0 * Dv);
        const float4* h1 = reinterpret_cast<const float4*>(h_s + c1 * Dv);
        const float4* h2 = reinterpret_cast<const float4*>(h_s + c2 * Dv);
        #pragma unroll 8
        for (int d4 = 0; d4 < 64; d4++) {
            float4 w4 = __ldg(&wrow[d4]);
            unsigned long long w01 = pk2(w4.x, w4.y), w23 = pk2(w4.z, w4.w);
            float4 v0 = h0[d4];
            ffma2(a00, pk2(v0.x, v0.y), w01); ffma2(a01, pk2(v0.z, v0.w), w23);
            float4 v1 = h1[d4];
            ffma2(a10, pk2(v1.x, v1.y), w01); ffma2(a11, pk2(v1.z, v1.w), w23);
            float4 v2 = h2[d4];
            ffma2(a20, pk2(v2.x, v2.y), w01); ffma2(a21, pk2(v2.z, v2.w), w23);
        }
        float sw = __ldg(&g_SW[r]), lb = __ldg(&g_LB[r]);
        float d0 = upksum(a00) + upksum(a01);
        float d1 = upksum(a10) + upksum(a11);
        float d2 = upksum(a20) + upksum(a21);
        hl_s[c0 * Rv + r] = rs_s[c0] * (d0 - mu_s[c0] * sw) + lb;
        hl_s[c1 * Rv + r] = rs_s[c1] * (d1 - mu_s[c1] * sw) + lb;
        if (w + 16 < Cv)
            hl_s[c2 * Rv + r] = rs_s[c2] * (d2 - mu_s[c2] * sw) + lb;
    }
    __syncwarp();   // hl rows produced & consumed by the same warp

    // ---- phase 5: R-space QKVG + l2norm + global_feat ---------------------
    {
        const int c0 = w, c1 = w + 8;
        const bool c2v = (w + 16 < Cv);
        const int c2 = c2v ? (w + 16) : (Cv - 1);
        float q0 = 0.f, q1 = 0.f, q2 = 0.f, k0 = 0.f, k1 = 0.f, k2 = 0.f;
        float v0 = 0.f, v1 = 0.f, v2 = 0.f, gg0 = 0.f, gg1 = 0.f, gg2 = 0.f;
        #pragma unroll 8
        for (int kk = 0; kk < 32; kk++) {
            float wq = __ldg(&Wq[kk * Rv + lane]);
            float wk = __ldg(&Wk[kk * Rv + lane]);
            float wv = __ldg(&Wv[kk * Rv + lane]);
            float wg = __ldg(&Wg[kk * Rv + lane]);
            float hv0 = hl_s[c0 * Rv + kk];
            float hv1 = hl_s[c1 * Rv + kk];
            float hv2 = hl_s[c2 * Rv + kk];
            q0 = fmaf(hv0, wq, q0); k0 = fmaf(hv0, wk, k0);
            v0 = fmaf(hv0, wv, v0); gg0 = fmaf(hv0, wg, gg0);
            q1 = fmaf(hv1, wq, q1); k1 = fmaf(hv1, wk, k1);
            v1 = fmaf(hv1, wv, v1); gg1 = fmaf(hv1, wg, gg1);
            q2 = fmaf(hv2, wq, q2); k2 = fmaf(hv2, wk, k2);
            v2 = fmaf(hv2, wv, v2); gg2 = fmaf(hv2, wg, gg2);
        }
        float bgl = __ldg(&bg[lane]);
        float gfa = 0.f;
        {
            float qs = q0 * q0, ks = k0 * k0;
            #pragma unroll
            for (int o = 16; o > 0; o >>= 1) {
                qs += __shfl_xor_sync(0xffffffffu, qs, o);
                ks += __shfl_xor_sync(0xffffffffu, ks, o);
            }
            float qn = q0 / fmaxf(sqrtf(qs), 1e-12f);
            float kn = k0 / fmaxf(sqrtf(ks), 1e-12f);
            A_s[c0 * Rv + lane] = qn * sigm(gg0 + bgl);
            gfa += kn * v0;
        }
        {
            float qs = q1 * q1, ks = k1 * k1;
            #pragma unroll
            for (int o = 16; o > 0; o >>= 1) {
                qs += __shfl_xor_sync(0xffffffffu, qs, o);
                ks += __shfl_xor_sync(0xffffffffu, ks, o);
            }
            float qn = q1 / fmaxf(sqrtf(qs), 1e-12f);
            float kn = k1 / fmaxf(sqrtf(ks), 1e-12f);
            A_s[c1 * Rv + lane] = qn * sigm(gg1 + bgl);
            gfa += kn * v1;
        }
        {
            float qs = q2 * q2, ks = k2 * k2;
            #pragma unroll
            for (int o = 16; o > 0; o >>= 1) {
                qs += __shfl_xor_sync(0xffffffffu, qs, o);
                ks += __shfl_xor_sync(0xffffffffu, ks, o);
            }
            if (c2v) {
                float qn = q2 / fmaxf(sqrtf(qs), 1e-12f);
                float kn = k2 / fmaxf(sqrtf(ks), 1e-12f);
                A_s[c2 * Rv + lane] = qn * sigm(gg2 + bgl);
                gfa += kn * v2;
            }
        }
        gf_s[w * Rv + lane] = gfa;
    }
    __syncthreads();   // A_s, gf partials, hid2_s all visible

    // ---- global_feat reduce (warp 0) + gate_val (all threads) -------------
    if (tid < 32) {
        float s = 0.f;
        #pragma unroll
        for (int ww = 0; ww < 8; ww++) s += gf_s[ww * Rv + tid];
        gf_s[tid] = s;
    }
    float epsv = __ldg(eps_p);
    float dc = __ldg(&dn2_b[tid]);
    #pragma unroll 8
    for (int j = 0; j < Hv; j++)
        dc += hid2_s[j] * __ldg(&dn2_w[j * Dv + tid]);
    float gv = sigm(__ldg(&g_logits[tid]) + epsv * dc);
    __syncthreads();   // gf_s[0..31] final

    // ---- phase 6: mixed = A@Wu (+bu), out = h + gate*mixed ----------------
    {
        unsigned long long wupk[16];
        #pragma unroll
        for (int r2 = 0; r2 < 16; r2++) {
            float wa = __ldg(&Wu[(2 * r2 + 0) * Dv + tid]) * gf_s[2 * r2 + 0];
            float wb = __ldg(&Wu[(2 * r2 + 1) * Dv + tid]) * gf_s[2 * r2 + 1];
            wupk[r2] = pk2(wa, wb);
        }
        float buv = __ldg(&bu[tid]);
        #pragma unroll
        for (int c = 0; c < Cv; c++) {
            const float4* arow = reinterpret_cast<const float4*>(A_s + c * Rv);
            unsigned long long acc0 = pk2(0.f, 0.f), acc1 = pk2(0.f, 0.f);
            #pragma unroll
            for (int r4 = 0; r4 < 8; r4++) {
                float4 a4 = arow[r4];
                ffma2(acc0, pk2(a4.x, a4.y), wupk[2 * r4 + 0]);
                ffma2(acc1, pk2(a4.z, a4.w), wupk[2 * r4 + 1]);
            }
            float mixed = upksum(acc0) + upksum(acc1) + buv;
            out[base + c * PDv] = h_s[c * Dv + tid] + gv * mixed;
        }
    }
}

// ---------------------------------------------------------------------------
extern "C" void kernel_launch(void* const* d_in, const int* in_sizes, int n_in,
                              void* d_out, int out_size) {
    const float* x     = (const float*)d_in[0];
    const float* ln_w  = (const float*)d_in[1];
    const float* ln_b  = (const float*)d_in[2];
    const float* Wd    = (const float*)d_in[3];
    const float* bd    = (const float*)d_in[4];
    const float* Wq    = (const float*)d_in[5];
    const float* Wk    = (const float*)d_in[6];
    const float* Wvp   = (const float*)d_in[7];
    const float* Wg    = (const float*)d_in[8];
    const float* bg    = (const float*)d_in[9];
    const float* Wu    = (const float*)d_in[10];
    const float* bu    = (const float*)d_in[11];
    const float* cn1_w = (const float*)d_in[12];
    const float* cn1_b = (const float*)d_in[13];
    const float* cn2_w = (const float*)d_in[14];
    const float* cn2_b = (const float*)d_in[15];
    const float* dn1_w = (const float*)d_in[16];
    const float* dn1_b = (const float*)d_in[17];
    const float* dn2_w = (const float*)d_in[18];
    const float* dn2_b = (const float*)d_in[19];
    const float* eps   = (const float*)d_in[20];
    float* out = (float*)d_out;

    prep_kernel<<<98, 256>>>(ln_w, ln_b, Wd, bd, cn1_w, cn1_b, cn2_w, cn2_b, dn1_w);
    hydra_kernel<<<BPv, 256>>>(x, Wq, Wk, Wvp, Wg, bg, Wu, bu,
                               dn1_b, dn2_w, dn2_b, eps, out);
}

// round 2
// speedup vs baseline: 1.8041x; 1.8041x over previous
#include <cuda_runtime.h>
#include <math.h>

#define Bv 64
#define Cv 21
#define Pv 96
#define Dv 256
#define Rv 32
#define Hv 64
#define BPv (Bv*Pv)
#define PDv (Pv*Dv)
#define CRv (Cv*Rv)

// ---------------- device-global scratch (allocation-free) -------------------
__device__ float g_Wd2[Dv*Rv];     // ln_w[d]*Wd[d][r], layout [d][r]
__device__ float g_W4[Rv*128];     // [kk][o]: o=0..31 Wq, 32..63 Wk, 64..95 Wv, 96..127 Wg
__device__ float g_SW[Rv];         // sum_d ln_w[d]*Wd[d][r]
__device__ float g_LB[Rv];         // sum_d ln_b[d]*Wd[d][r] + bd[r]
__device__ float g_logits[Dv];     // channel logits
__device__ float g_cv[BPv*Dv];     // channel variance per (bp,d)
__device__ float g_A[BPv*CRv];     // qn * sigmoid-gate
__device__ float g_gf[BPv*Rv];     // global_feat
__device__ float g_gate[BPv*Dv];   // final gate value

static __device__ __forceinline__ float geluf(float x) {
    return 0.5f * x * (1.0f + erff(x * 0.70710678118654752f));
}
static __device__ __forceinline__ float sigm(float x) {
    return 1.0f / (1.0f + expf(-x));
}
static __device__ __forceinline__ unsigned long long pk2(float a, float b) {
    unsigned long long r;
    asm("mov.b64 %0, {%1,%2};" : "=l"(r) : "f"(a), "f"(b));
    return r;
}
static __device__ __forceinline__ void ffma2(unsigned long long& d,
                                             unsigned long long a,
                                             unsigned long long b) {
    asm("fma.rn.f32x2 %0, %1, %2, %3;" : "=l"(d) : "l"(a), "l"(b), "l"(d));
}
static __device__ __forceinline__ float upksum(unsigned long long v) {
    float lo, hi;
    asm("mov.b64 {%0,%1}, %2;" : "=f"(lo), "=f"(hi) : "l"(v));
    return lo + hi;
}

// ---------------------------------------------------------------------------
// Prep: 50 blocks x 256 threads
// ---------------------------------------------------------------------------
__global__ void prep_kernel(const float* __restrict__ ln_w, const float* __restrict__ ln_b,
                            const float* __restrict__ Wd,   const float* __restrict__ bd,
                            const float* __restrict__ Wq,   const float* __restrict__ Wk,
                            const float* __restrict__ Wv,   const float* __restrict__ Wg,
                            const float* __restrict__ cn1_w, const float* __restrict__ cn1_b,
                            const float* __restrict__ cn2_w, const float* __restrict__ cn2_b) {
    int bi = blockIdx.x, tid = threadIdx.x;
    if (bi < 32) {
        int idx = bi * 256 + tid;            // d*32+r
        g_Wd2[idx] = ln_w[idx >> 5] * Wd[idx];
    } else if (bi < 48) {
        int idx = (bi - 32) * 256 + tid;     // kk*128+o
        int kk = idx >> 7, o = idx & 127, m = o >> 5, r = o & 31;
        const float* src = (m == 0) ? Wq : (m == 1) ? Wk : (m == 2) ? Wv : Wg;
        g_W4[idx] = src[kk * Rv + r];
    } else if (bi == 48) {
        __shared__ float ssw[8][32], slb[8][32];
        int r = tid & 31, seg = tid >> 5;
        float sw = 0.f, lb = 0.f;
        for (int dd = 0; dd < 32; dd++) {
            int d = seg * 32 + dd;
            float wv = Wd[d * Rv + r];
            sw += ln_w[d] * wv;
            lb += ln_b[d] * wv;
        }
        ssw[seg][r] = sw; slb[seg][r] = lb;
        __syncthreads();
        if (tid < 32) {
            float a = 0.f, b2 = 0.f;
            #pragma unroll
            for (int s = 0; s < 8; s++) { a += ssw[s][tid]; b2 += slb[s][tid]; }
            g_SW[tid] = a;
            g_LB[tid] = b2 + bd[tid];
        }
    } else {
        __shared__ float hid[Hv];
        const float lc = logf(21.0f) / logf(1000.0f);
        if (tid < Hv) hid[tid] = geluf(lc * cn1_w[tid] + cn1_b[tid]);
        __syncthreads();
        float acc = cn2_b[tid];
        for (int j = 0; j < Hv; j++) acc += hid[j] * cn2_w[j * Dv + tid];
        g_logits[tid] = acc;
    }
}

// ---------------------------------------------------------------------------
// K1 helpers: warp-split-K down-projection and stacked QKVG
// ---------------------------------------------------------------------------
template<int NC>
static __device__ __forceinline__ void ph4_pass(const float* __restrict__ hrow0,
                                                int lane, int d0,
                                                float* __restrict__ dst) {
    unsigned long long acc[NC];
    #pragma unroll
    for (int j = 0; j < NC; j++) acc[j] = 0ull;
    #pragma unroll
    for (int i = 0; i < 8; i++) {
        int d = d0 + 4 * i;
        float w0 = __ldg(&g_Wd2[(d + 0) * Rv + lane]);
        float w1 = __ldg(&g_Wd2[(d + 1) * Rv + lane]);
        float w2 = __ldg(&g_Wd2[(d + 2) * Rv + lane]);
        float w3 = __ldg(&g_Wd2[(d + 3) * Rv + lane]);
        unsigned long long w01 = pk2(w0, w1), w23 = pk2(w2, w3);
        #pragma unroll
        for (int j = 0; j < NC; j++) {
            float4 h4 = *reinterpret_cast<const float4*>(hrow0 + j * Dv + d);
            ffma2(acc[j], pk2(h4.x, h4.y), w01);
            ffma2(acc[j], pk2(h4.z, h4.w), w23);
        }
    }
    #pragma unroll
    for (int j = 0; j < NC; j++) dst[j * Rv + lane] = upksum(acc[j]);
}

template<int NC>
static __device__ __forceinline__ void ph5_pass(const float* __restrict__ hl0,
                                                int o, float* __restrict__ val) {
    unsigned long long acc[NC];
    #pragma unroll
    for (int j = 0; j < NC; j++) acc[j] = 0ull;
    #pragma unroll
    for (int i = 0; i < 8; i++) {
        int kk = 4 * i;
        float w0 = __ldg(&g_W4[(kk + 0) * 128 + o]);
        float w1 = __ldg(&g_W4[(kk + 1) * 128 + o]);
        float w2 = __ldg(&g_W4[(kk + 2) * 128 + o]);
        float w3 = __ldg(&g_W4[(kk + 3) * 128 + o]);
        unsigned long long w01 = pk2(w0, w1), w23 = pk2(w2, w3);
        #pragma unroll
        for (int j = 0; j < NC; j++) {
            float4 h4 = *reinterpret_cast<const float4*>(hl0 + j * Rv + kk);
            ffma2(acc[j], pk2(h4.x, h4.y), w01);
            ffma2(acc[j], pk2(h4.z, h4.w), w23);
        }
    }
    #pragma unroll
    for (int j = 0; j < NC; j++) val[j] = upksum(acc[j]);
}

// ---------------------------------------------------------------------------
// K1: per-bp front half (cv, LN, h_low, QKVG, A, gf). grid=6144, 256 thr
// ---------------------------------------------------------------------------
__global__ __launch_bounds__(256, 2) void k1_kernel(const float* __restrict__ x,
                                                    const float* __restrict__ bg) {
    __shared__ __align__(16) float h_s[Cv * Dv];
    __shared__ __align__(16) float sP[8 * CRv];
    __shared__ __align__(16) float hl_s[CRv];
    __shared__ float mu_s[Cv], rs_s[Cv];
    __shared__ float gfp_s[8 * Rv];

    const int tid = threadIdx.x;
    const int lane = tid & 31;
    const int w = tid >> 5;
    const int bp = blockIdx.x;
    const int b = bp / Pv, p = bp % Pv;
    const int base = b * Cv * PDv + p * Dv + tid;

    // phase 1: load tile + channel variance
    float s1 = 0.f, s2 = 0.f;
    #pragma unroll
    for (int c = 0; c < Cv; c++) {
        float v = x[base + c * PDv];
        h_s[c * Dv + tid] = v;
        s1 += v; s2 += v * v;
    }
    g_cv[bp * Dv + tid] = (s2 - s1 * s1 * (1.0f / 21.0f)) * (1.0f / 20.0f);
    __syncthreads();

    // phase 2: LN row stats (warp w owns rows w, w+8, w+16)
    #pragma unroll
    for (int ci = 0; ci < 3; ci++) {
        int c = w + 8 * ci;
        if (c < Cv) {
            float s = 0.f, ss = 0.f;
            #pragma unroll
            for (int k = 0; k < 8; k++) {
                float v = h_s[c * Dv + lane + 32 * k];
                s += v; ss += v * v;
            }
            #pragma unroll
            for (int o = 16; o > 0; o >>= 1) {
                s  += __shfl_xor_sync(0xffffffffu, s, o);
                ss += __shfl_xor_sync(0xffffffffu, ss, o);
            }
            if (lane == 0) {
                float mu = s * (1.0f / 256.0f);
                float var = ss * (1.0f / 256.0f) - mu * mu;
                mu_s[c] = mu;
                rs_s[c] = rsqrtf(var + 1e-5f);
            }
        }
    }

    // phase 4: warp-split-K partial GEMM (warp w handles d in [32w,32w+32))
    ph4_pass<11>(h_s,            lane, 32 * w, sP + (w * Cv +  0) * Rv);
    ph4_pass<10>(h_s + 11 * Dv,  lane, 32 * w, sP + (w * Cv + 11) * Rv);
    __syncthreads();

    // reduce partials + LN fold
    for (int idx = tid; idx < CRv; idx += 256) {
        int c = idx >> 5, r = idx & 31;
        float s = 0.f;
        #pragma unroll
        for (int w8 = 0; w8 < 8; w8++) s += sP[w8 * CRv + idx];
        hl_s[idx] = rs_s[c] * (s - mu_s[c] * __ldg(&g_SW[r])) + __ldg(&g_LB[r]);
    }
    __syncthreads();

    // phase 5: stacked QKVG. o = output col (q/k/v/g x r), two channel groups
    {
        const int o = tid & 127, grp = tid >> 7;
        const int m = o >> 5, r = o & 31;
        const int nc = grp ? 10 : 11;
        float val[11];
        if (grp == 0) ph5_pass<11>(hl_s, o, val);
        else          ph5_pass<10>(hl_s + 11 * Rv, o, val);

        float* dst = sP + m * CRv + (grp * 11) * Rv;   // reuse sP
        if (m < 2) {
            #pragma unroll
            for (int j = 0; j < 11; j++) if (j < nc) {
                float q = val[j];
                float qs = q * q;
                #pragma unroll
                for (int off = 16; off > 0; off >>= 1)
                    qs += __shfl_xor_sync(0xffffffffu, qs, off);
                dst[j * Rv + r] = q / fmaxf(sqrtf(qs), 1e-12f);
            }
        } else if (m == 2) {
            #pragma unroll
            for (int j = 0; j < 11; j++) if (j < nc)
                dst[j * Rv + r] = val[j];
        } else {
            float bgr = __ldg(&bg[r]);
            #pragma unroll
            for (int j = 0; j < 11; j++) if (j < nc)
                dst[j * Rv + r] = sigm(val[j] + bgr);
        }
    }
    __syncthreads();

    // combine: A = qn*gate, gf partial = kn*v
    {
        const int r2 = tid & 31, cg = tid >> 5;
        float gfp = 0.f;
        #pragma unroll
        for (int ci = 0; ci < 3; ci++) {
            int c = cg + 8 * ci;
            if (c < Cv) {
                float qn = sP[0 * CRv + c * Rv + r2];
                float gs = sP[3 * CRv + c * Rv + r2];
                g_A[bp * CRv + c * Rv + r2] = qn * gs;
                gfp += sP[1 * CRv + c * Rv + r2] * sP[2 * CRv + c * Rv + r2];
            }
        }
        gfp_s[cg * Rv + r2] = gfp;
    }
    __syncthreads();
    if (tid < Rv) {
        float s = 0.f;
        #pragma unroll
        for (int cg = 0; cg < 8; cg++) s += gfp_s[cg * Rv + tid];
        g_gf[bp * Rv + tid] = s;
    }
}

// ---------------------------------------------------------------------------
// K2: gate MLP as batched GEMM. grid=192, 256 thr, 32 bp-rows per CTA
// ---------------------------------------------------------------------------
__global__ __launch_bounds__(256) void k2_kernel(const float* __restrict__ dn1_w,
                                                 const float* __restrict__ dn1_b,
                                                 const float* __restrict__ dn2_w,
                                                 const float* __restrict__ dn2_b,
                                                 const float* __restrict__ eps_p) {
    __shared__ float cv_s[32 * 257];
    __shared__ __align__(16) float hid_s[32 * 68];
    const int tid = threadIdx.x;
    const int bp0 = blockIdx.x * 32;

    #pragma unroll
    for (int i = 0; i < 32; i++)
        cv_s[i * 257 + tid] = __ldg(&g_cv[(bp0 + i) * Dv + tid]);
    __syncthreads();

    // GEMM1: hid[bp][j] = gelu(cv[bp] . dn1[:,j] + b1[j])
    {
        const int bpl = tid & 31, jg = tid >> 5;
        const int j0 = jg * 8;
        float4 b1a = __ldg((const float4*)&dn1_b[j0]);
        float4 b1b = __ldg((const float4*)&dn1_b[j0 + 4]);
        float acc[8];
        #pragma unroll
        for (int k = 0; k < 8; k++) acc[k] = 0.f;
        #pragma unroll 4
        for (int d = 0; d < Dv; d++) {
            float cvv = cv_s[bpl * 257 + d];
            float4 wa = __ldg((const float4*)&dn1_w[d * Hv + j0]);
            float4 wb = __ldg((const float4*)&dn1_w[d * Hv + j0 + 4]);
            acc[0] = fmaf(cvv, wa.x, acc[0]); acc[1] = fmaf(cvv, wa.y, acc[1]);
            acc[2] = fmaf(cvv, wa.z, acc[2]); acc[3] = fmaf(cvv, wa.w, acc[3]);
            acc[4] = fmaf(cvv, wb.x, acc[4]); acc[5] = fmaf(cvv, wb.y, acc[5]);
            acc[6] = fmaf(cvv, wb.z, acc[6]); acc[7] = fmaf(cvv, wb.w, acc[7]);
        }
        hid_s[bpl * 68 + j0 + 0] = geluf(acc[0] + b1a.x);
        hid_s[bpl * 68 + j0 + 1] = geluf(acc[1] + b1a.y);
        hid_s[bpl * 68 + j0 + 2] = geluf(acc[2] + b1a.z);
        hid_s[bpl * 68 + j0 + 3] = geluf(acc[3] + b1a.w);
        hid_s[bpl * 68 + j0 + 4] = geluf(acc[4] + b1b.x);
        hid_s[bpl * 68 + j0 + 5] = geluf(acc[5] + b1b.y);
        hid_s[bpl * 68 + j0 + 6] = geluf(acc[6] + b1b.z);
        hid_s[bpl * 68 + j0 + 7] = geluf(acc[7] + b1b.w);
    }
    __syncthreads();

    // GEMM2 + gate: thread owns column d = tid, 32 bp rows
    {
        const int d = tid;
        float acc2[32];
        #pragma unroll
        for (int k = 0; k < 32; k++) acc2[k] = 0.f;
        #pragma unroll 4
        for (int j4 = 0; j4 < 16; j4++) {
            int j = 4 * j4;
            float w0 = __ldg(&dn2_w[(j + 0) * Dv + d]);
            float w1 = __ldg(&dn2_w[(j + 1) * Dv + d]);
            float w2 = __ldg(&dn2_w[(j + 2) * Dv + d]);
            float w3 = __ldg(&dn2_w[(j + 3) * Dv + d]);
            #pragma unroll
            for (int bpl = 0; bpl < 32; bpl++) {
                float4 h4 = *(const float4*)&hid_s[bpl * 68 + j];
                acc2[bpl] = fmaf(h4.x, w0, fmaf(h4.y, w1,
                            fmaf(h4.z, w2, fmaf(h4.w, w3, acc2[bpl]))));
            }
        }
        float lg = __ldg(&g_logits[d]);
        float b2 = __ldg(&dn2_b[d]);
        float ev = __ldg(eps_p);
        #pragma unroll
        for (int bpl = 0; bpl < 32; bpl++)
            g_gate[(bp0 + bpl) * Dv + d] = sigm(lg + ev * (acc2[bpl] + b2));
    }
}

// ---------------------------------------------------------------------------
// K3: out = x + gate * (A' @ Wu + bu). grid=6144, 128 thr (2 d-cols/thread)
// ---------------------------------------------------------------------------
__global__ __launch_bounds__(128) void k3_kernel(const float* __restrict__ x,
                                                 const float* __restrict__ Wu,
                                                 const float* __restrict__ bu,
                                                 float* __restrict__ out) {
    __shared__ __align__(16) float A_sm[CRv];
    __shared__ float gf_s[Rv];
    const int tid = threadIdx.x;
    const int bp = blockIdx.x;
    const int b = bp / Pv, p = bp % Pv;

    if (tid < Rv) gf_s[tid] = __ldg(&g_gf[bp * Rv + tid]);
    __syncthreads();
    for (int idx = tid; idx < CRv; idx += 128)
        A_sm[idx] = __ldg(&g_A[bp * CRv + idx]) * gf_s[idx & 31];
    __syncthreads();

    const int d0 = tid, d1 = tid + 128;
    unsigned long long wf0[16], wf1[16];
    #pragma unroll
    for (int r2 = 0; r2 < 16; r2++) {
        wf0[r2] = pk2(__ldg(&Wu[(2 * r2) * Dv + d0]), __ldg(&Wu[(2 * r2 + 1) * Dv + d0]));
        wf1[r2] = pk2(__ldg(&Wu[(2 * r2) * Dv + d1]), __ldg(&Wu[(2 * r2 + 1) * Dv + d1]));
    }
    const float bu0 = __ldg(&bu[d0]), bu1 = __ldg(&bu[d1]);
    const float gv0 = __ldg(&g_gate[bp * Dv + d0]);
    const float gv1 = __ldg(&g_gate[bp * Dv + d1]);
    const int base = b * Cv * PDv + p * Dv + tid;

    #pragma unroll
    for (int c = 0; c < Cv; c++) {
        const float4* ar = (const float4*)&A_sm[c * Rv];
        unsigned long long acc0 = 0ull, acc1 = 0ull;
        #pragma unroll
        for (int r4 = 0; r4 < 8; r4++) {
            float4 a4 = ar[r4];
            unsigned long long p01 = pk2(a4.x, a4.y), p23 = pk2(a4.z, a4.w);
            ffma2(acc0, p01, wf0[2 * r4]); ffma2(acc0, p23, wf0[2 * r4 + 1]);
            ffma2(acc1, p01, wf1[2 * r4]); ffma2(acc1, p23, wf1[2 * r4 + 1]);
        }
        float m0 = upksum(acc0) + bu0;
        float m1 = upksum(acc1) + bu1;
        int g = base + c * PDv;
        out[g]       = x[g]       + gv0 * m0;
        out[g + 128] = x[g + 128] + gv1 * m1;
    }
}

// ---------------------------------------------------------------------------
extern "C" void kernel_launch(void* const* d_in, const int* in_sizes, int n_in,
                              void* d_out, int out_size) {
    const float* x     = (const float*)d_in[0];
    const float* ln_w  = (const float*)d_in[1];
    const float* ln_b  = (const float*)d_in[2];
    const float* Wd    = (const float*)d_in[3];
    const float* bd    = (const float*)d_in[4];
    const float* Wq    = (const float*)d_in[5];
    const float* Wk    = (const float*)d_in[6];
    const float* Wvp   = (const float*)d_in[7];
    const float* Wg    = (const float*)d_in[8];
    const float* bg    = (const float*)d_in[9];
    const float* Wu    = (const float*)d_in[10];
    const float* bu    = (const float*)d_in[11];
    const float* cn1_w = (const float*)d_in[12];
    const float* cn1_b = (const float*)d_in[13];
    const float* cn2_w = (const float*)d_in[14];
    const float* cn2_b = (const float*)d_in[15];
    const float* dn1_w = (const float*)d_in[16];
    const float* dn1_b = (const float*)d_in[17];
    const float* dn2_w = (const float*)d_in[18];
    const float* dn2_b = (const float*)d_in[19];
    const float* eps   = (const float*)d_in[20];
    float* out = (float*)d_out;

    prep_kernel<<<50, 256>>>(ln_w, ln_b, Wd, bd, Wq, Wk, Wvp, Wg,
                             cn1_w, cn1_b, cn2_w, cn2_b);
    k1_kernel<<<BPv, 256>>>(x, bg);
    k2_kernel<<<BPv / 32, 256>>>(dn1_w, dn1_b, dn2_w, dn2_b, eps);
    k3_kernel<<<BPv, 128>>>(x, Wu, bu, out);
}

// round 3
// speedup vs baseline: 1.9895x; 1.1028x over previous
#include <cuda_runtime.h>
#include <math.h>

#define Bv 64
#define Cv 21
#define Pv 96
#define Dv 256
#define Rv 32
#define Hv 64
#define BPv (Bv*Pv)
#define PDv (Pv*Dv)
#define CRv (Cv*Rv)

// ---------------- device-global precomputed weights -------------------------
__device__ float g_Wd2[Dv*Rv];     // ln_w[d]*Wd[d][r], layout [d][r]
__device__ float g_W4[Rv*128];     // [kk][o]: o=0..31 Wq, 32..63 Wk, 64..95 Wv, 96..127 Wg
__device__ float g_dn1T[Hv*Dv];    // [j][d] = dn1_w[d][j]
__device__ float g_SW[Rv];         // sum_d ln_w[d]*Wd[d][r]
__device__ float g_LB[Rv];         // sum_d ln_b[d]*Wd[d][r] + bd[r]
__device__ float g_logits[Dv];     // channel logits (bp-invariant)

static __device__ __forceinline__ float geluf(float x) {
    return 0.5f * x * (1.0f + erff(x * 0.70710678118654752f));
}
static __device__ __forceinline__ float sigm(float x) {
    return 1.0f / (1.0f + expf(-x));
}
static __device__ __forceinline__ unsigned long long pk2(float a, float b) {
    unsigned long long r;
    asm("mov.b64 %0, {%1,%2};" : "=l"(r) : "f"(a), "f"(b));
    return r;
}
static __device__ __forceinline__ void ffma2(unsigned long long& d,
                                             unsigned long long a,
                                             unsigned long long b) {
    asm("fma.rn.f32x2 %0, %1, %2, %3;" : "=l"(d) : "l"(a), "l"(b), "l"(d));
}
static __device__ __forceinline__ float upksum(unsigned long long v) {
    float lo, hi;
    asm("mov.b64 {%0,%1}, %2;" : "=f"(lo), "=f"(hi) : "l"(v));
    return lo + hi;
}

// ---------------------------------------------------------------------------
// Prep: 114 blocks x 256 threads
// ---------------------------------------------------------------------------
__global__ void prep_kernel(const float* __restrict__ ln_w, const float* __restrict__ ln_b,
                            const float* __restrict__ Wd,   const float* __restrict__ bd,
                            const float* __restrict__ Wq,   const float* __restrict__ Wk,
                            const float* __restrict__ Wv,   const float* __restrict__ Wg,
                            const float* __restrict__ cn1_w, const float* __restrict__ cn1_b,
                            const float* __restrict__ cn2_w, const float* __restrict__ cn2_b,
                            const float* __restrict__ dn1_w) {
    int bi = blockIdx.x, tid = threadIdx.x;
    if (bi < 32) {
        int idx = bi * 256 + tid;            // d*32+r
        g_Wd2[idx] = ln_w[idx >> 5] * Wd[idx];
    } else if (bi < 48) {
        int idx = (bi - 32) * 256 + tid;     // kk*128+o
        int kk = idx >> 7, o = idx & 127, m = o >> 5, r = o & 31;
        const float* src = (m == 0) ? Wq : (m == 1) ? Wk : (m == 2) ? Wv : Wg;
        g_W4[idx] = src[kk * Rv + r];
    } else if (bi < 112) {
        int j = bi - 48;
        g_dn1T[j * Dv + tid] = dn1_w[tid * Hv + j];
    } else if (bi == 112) {
        __shared__ float ssw[8][32], slb[8][32];
        int r = tid & 31, seg = tid >> 5;
        float sw = 0.f, lb = 0.f;
        for (int dd = 0; dd < 32; dd++) {
            int d = seg * 32 + dd;
            float wv = Wd[d * Rv + r];
            sw += ln_w[d] * wv;
            lb += ln_b[d] * wv;
        }
        ssw[seg][r] = sw; slb[seg][r] = lb;
        __syncthreads();
        if (tid < 32) {
            float a = 0.f, b2 = 0.f;
            #pragma unroll
            for (int s = 0; s < 8; s++) { a += ssw[s][tid]; b2 += slb[s][tid]; }
            g_SW[tid] = a;
            g_LB[tid] = b2 + bd[tid];
        }
    } else {
        __shared__ float hid[Hv];
        const float lc = logf(21.0f) / logf(1000.0f);
        if (tid < Hv) hid[tid] = geluf(lc * cn1_w[tid] + cn1_b[tid]);
        __syncthreads();
        float acc = cn2_b[tid];
        for (int j = 0; j < Hv; j++) acc += hid[j] * cn2_w[j * Dv + tid];
        g_logits[tid] = acc;
    }
}

// ---------------------------------------------------------------------------
// Fused kernel helpers
// ---------------------------------------------------------------------------
template<int NC>
static __device__ __forceinline__ void ph4_pass(const float* __restrict__ hrow0,
                                                int lane, int d0,
                                                float* __restrict__ dst) {
    unsigned long long acc[NC];
    #pragma unroll
    for (int j = 0; j < NC; j++) acc[j] = 0ull;
    #pragma unroll
    for (int i = 0; i < 8; i++) {
        int d = d0 + 4 * i;
        float w0 = __ldg(&g_Wd2[(d + 0) * Rv + lane]);
        float w1 = __ldg(&g_Wd2[(d + 1) * Rv + lane]);
        float w2 = __ldg(&g_Wd2[(d + 2) * Rv + lane]);
        float w3 = __ldg(&g_Wd2[(d + 3) * Rv + lane]);
        unsigned long long w01 = pk2(w0, w1), w23 = pk2(w2, w3);
        #pragma unroll
        for (int j = 0; j < NC; j++) {
            float4 h4 = *reinterpret_cast<const float4*>(hrow0 + j * Dv + d);
            ffma2(acc[j], pk2(h4.x, h4.y), w01);
            ffma2(acc[j], pk2(h4.z, h4.w), w23);
        }
    }
    #pragma unroll
    for (int j = 0; j < NC; j++) dst[j * Rv + lane] = upksum(acc[j]);
}

template<int NC>
static __device__ __forceinline__ void ph5_pass(const float* __restrict__ hl0,
                                                int o, float* __restrict__ val) {
    unsigned long long acc[NC];
    #pragma unroll
    for (int j = 0; j < NC; j++) acc[j] = 0ull;
    #pragma unroll
    for (int i = 0; i < 8; i++) {
        int kk = 4 * i;
        float w0 = __ldg(&g_W4[(kk + 0) * 128 + o]);
        float w1 = __ldg(&g_W4[(kk + 1) * 128 + o]);
        float w2 = __ldg(&g_W4[(kk + 2) * 128 + o]);
        float w3 = __ldg(&g_W4[(kk + 3) * 128 + o]);
        unsigned long long w01 = pk2(w0, w1), w23 = pk2(w2, w3);
        #pragma unroll
        for (int j = 0; j < NC; j++) {
            float4 h4 = *reinterpret_cast<const float4*>(hl0 + j * Rv + kk);
            ffma2(acc[j], pk2(h4.x, h4.y), w01);
            ffma2(acc[j], pk2(h4.z, h4.w), w23);
        }
    }
    #pragma unroll
    for (int j = 0; j < NC; j++) val[j] = upksum(acc[j]);
}

// ---------------------------------------------------------------------------
// Fully-fused kernel: one CTA per (b,p). 256 threads, 8 warps.
// ---------------------------------------------------------------------------
__global__ __launch_bounds__(256, 2) void fused_kernel(
    const float* __restrict__ x,
    const float* __restrict__ bg,
    const float* __restrict__ Wu, const float* __restrict__ bu,
    const float* __restrict__ dn1_b,
    const float* __restrict__ dn2_w, const float* __restrict__ dn2_b,
    const float* __restrict__ eps_p,
    float* __restrict__ out)
{
    __shared__ __align__(16) float h_s[Cv * Dv];     // raw tile
    __shared__ __align__(16) float sP[8 * CRv];      // split-K partials / QKVG
    __shared__ __align__(16) float hl_s[CRv];        // h_low, then A (=qn*gate)
    __shared__ __align__(16) float cv_s[Dv];         // channel variance
    __shared__ float mu_s[Cv], rs_s[Cv];
    __shared__ float gfp_s[8 * Rv];
    __shared__ float gf_s[Rv];
    __shared__ __align__(16) float hid_s[Hv];        // data-MLP hidden
    __shared__ float gate_s[Dv];                     // final gate

    const int tid = threadIdx.x;
    const int lane = tid & 31;
    const int w = tid >> 5;
    const int bp = blockIdx.x;
    const int b = bp / Pv, p = bp % Pv;
    const int base = b * Cv * PDv + p * Dv + tid;

    // ---- phase 1: load tile + channel variance ---------------------------
    float s1 = 0.f, s2 = 0.f;
    #pragma unroll
    for (int c = 0; c < Cv; c++) {
        float v = x[base + c * PDv];
        h_s[c * Dv + tid] = v;
        s1 += v; s2 += v * v;
    }
    cv_s[tid] = (s2 - s1 * s1 * (1.0f / 21.0f)) * (1.0f / 20.0f);
    __syncthreads();

    // ---- phase 2: LN row stats -------------------------------------------
    #pragma unroll
    for (int ci = 0; ci < 3; ci++) {
        int c = w + 8 * ci;
        if (c < Cv) {
            float s = 0.f, ss = 0.f;
            #pragma unroll
            for (int k = 0; k < 8; k++) {
                float v = h_s[c * Dv + lane + 32 * k];
                s += v; ss += v * v;
            }
            #pragma unroll
            for (int o = 16; o > 0; o >>= 1) {
                s  += __shfl_xor_sync(0xffffffffu, s, o);
                ss += __shfl_xor_sync(0xffffffffu, ss, o);
            }
            if (lane == 0) {
                float mu = s * (1.0f / 256.0f);
                float var = ss * (1.0f / 256.0f) - mu * mu;
                mu_s[c] = mu;
                rs_s[c] = rsqrtf(var + 1e-5f);
            }
        }
    }

    // ---- phase 3: gate MLP GEMM1: hid = gelu(cv @ dn1 + b1) --------------
    {
        float4 ca = *reinterpret_cast<const float4*>(&cv_s[4 * lane]);
        float4 cb = *reinterpret_cast<const float4*>(&cv_s[128 + 4 * lane]);
        #pragma unroll
        for (int jj = 0; jj < 8; jj++) {
            int j = w * 8 + jj;
            float4 wa = __ldg((const float4*)&g_dn1T[j * Dv + 4 * lane]);
            float4 wb = __ldg((const float4*)&g_dn1T[j * Dv + 128 + 4 * lane]);
            float part = ca.x * wa.x + ca.y * wa.y + ca.z * wa.z + ca.w * wa.w
                       + cb.x * wb.x + cb.y * wb.y + cb.z * wb.z + cb.w * wb.w;
            #pragma unroll
            for (int o = 16; o > 0; o >>= 1)
                part += __shfl_xor_sync(0xffffffffu, part, o);
            if (lane == 0) hid_s[j] = geluf(part + __ldg(&dn1_b[j]));
        }
    }

    // ---- phase 4: warp-split-K down-projection ---------------------------
    ph4_pass<11>(h_s,           lane, 32 * w, sP + (w * Cv +  0) * Rv);
    ph4_pass<10>(h_s + 11 * Dv, lane, 32 * w, sP + (w * Cv + 11) * Rv);
    __syncthreads();

    // ---- reduce partials + LN fold -> hl_s -------------------------------
    for (int idx = tid; idx < CRv; idx += 256) {
        int c = idx >> 5, r = idx & 31;
        float s = 0.f;
        #pragma unroll
        for (int w8 = 0; w8 < 8; w8++) s += sP[w8 * CRv + idx];
        hl_s[idx] = rs_s[c] * (s - mu_s[c] * __ldg(&g_SW[r])) + __ldg(&g_LB[r]);
    }

    // ---- gate MLP GEMM2 + sigmoid -> gate_s (thread owns d=tid) ----------
    {
        float dc = 0.f;
        #pragma unroll 4
        for (int j4 = 0; j4 < 16; j4++) {
            int j = 4 * j4;
            float4 h4 = *reinterpret_cast<const float4*>(&hid_s[j]);
            float w0 = __ldg(&dn2_w[(j + 0) * Dv + tid]);
            float w1 = __ldg(&dn2_w[(j + 1) * Dv + tid]);
            float w2 = __ldg(&dn2_w[(j + 2) * Dv + tid]);
            float w3 = __ldg(&dn2_w[(j + 3) * Dv + tid]);
            dc = fmaf(h4.x, w0, fmaf(h4.y, w1, fmaf(h4.z, w2, fmaf(h4.w, w3, dc))));
        }
        float ev = __ldg(eps_p);
        gate_s[tid] = sigm(__ldg(&g_logits[tid]) + ev * (dc + __ldg(&dn2_b[tid])));
    }
    __syncthreads();

    // ---- phase 5: stacked QKVG -------------------------------------------
    {
        const int o = tid & 127, grp = tid >> 7;
        const int m = o >> 5, r = o & 31;
        const int nc = grp ? 10 : 11;
        float val[11];
        if (grp == 0) ph5_pass<11>(hl_s, o, val);
        else          ph5_pass<10>(hl_s + 11 * Rv, o, val);

        float* dst = sP + m * CRv + (grp * 11) * Rv;
        if (m < 2) {
            #pragma unroll
            for (int j = 0; j < 11; j++) if (j < nc) {
                float q = val[j];
                float qs = q * q;
                #pragma unroll
                for (int off = 16; off > 0; off >>= 1)
                    qs += __shfl_xor_sync(0xffffffffu, qs, off);
                dst[j * Rv + r] = q / fmaxf(sqrtf(qs), 1e-12f);
            }
        } else if (m == 2) {
            #pragma unroll
            for (int j = 0; j < 11; j++) if (j < nc)
                dst[j * Rv + r] = val[j];
        } else {
            float bgr = __ldg(&bg[r]);
            #pragma unroll
            for (int j = 0; j < 11; j++) if (j < nc)
                dst[j * Rv + r] = sigm(val[j] + bgr);
        }
    }
    __syncthreads();

    // ---- combine: A = qn*gate into hl_s; gf partials ---------------------
    {
        const int r2 = tid & 31, cg = tid >> 5;
        float gfp = 0.f;
        #pragma unroll
        for (int ci = 0; ci < 3; ci++) {
            int c = cg + 8 * ci;
            if (c < Cv) {
                float qn = sP[0 * CRv + c * Rv + r2];
                float gs = sP[3 * CRv + c * Rv + r2];
                hl_s[c * Rv + r2] = qn * gs;
                gfp += sP[1 * CRv + c * Rv + r2] * sP[2 * CRv + c * Rv + r2];
            }
        }
        gfp_s[cg * Rv + r2] = gfp;
    }
    __syncthreads();
    if (tid < Rv) {
        float s = 0.f;
        #pragma unroll
        for (int cg = 0; cg < 8; cg++) s += gfp_s[cg * Rv + tid];
        gf_s[tid] = s;
    }
    __syncthreads();

    // ---- phase 6: mixed = A @ (Wu*gf) + bu; out = h + gate*mixed ---------
    {
        unsigned long long wf[16];
        #pragma unroll
        for (int r2 = 0; r2 < 16; r2++) {
            float wa = __ldg(&Wu[(2 * r2 + 0) * Dv + tid]) * gf_s[2 * r2 + 0];
            float wb = __ldg(&Wu[(2 * r2 + 1) * Dv + tid]) * gf_s[2 * r2 + 1];
            wf[r2] = pk2(wa, wb);
        }
        const float buv = __ldg(&bu[tid]);
        const float gv = gate_s[tid];
        #pragma unroll
        for (int c = 0; c < Cv; c++) {
            const float4* ar = reinterpret_cast<const float4*>(&hl_s[c * Rv]);
            unsigned long long acc0 = 0ull, acc1 = 0ull;
            #pragma unroll
            for (int r4 = 0; r4 < 4; r4++) {
                float4 a4 = ar[2 * r4];
                float4 b4 = ar[2 * r4 + 1];
                ffma2(acc0, pk2(a4.x, a4.y), wf[4 * r4 + 0]);
                ffma2(acc1, pk2(a4.z, a4.w), wf[4 * r4 + 1]);
                ffma2(acc0, pk2(b4.x, b4.y), wf[4 * r4 + 2]);
                ffma2(acc1, pk2(b4.z, b4.w), wf[4 * r4 + 3]);
            }
            float mixed = upksum(acc0) + upksum(acc1) + buv;
            out[base + c * PDv] = h_s[c * Dv + tid] + gv * mixed;
        }
    }
}

// ---------------------------------------------------------------------------
extern "C" void kernel_launch(void* const* d_in, const int* in_sizes, int n_in,
                              void* d_out, int out_size) {
    const float* x     = (const float*)d_in[0];
    const float* ln_w  = (const float*)d_in[1];
    const float* ln_b  = (const float*)d_in[2];
    const float* Wd    = (const float*)d_in[3];
    const float* bd    = (const float*)d_in[4];
    const float* Wq    = (const float*)d_in[5];
    const float* Wk    = (const float*)d_in[6];
    const float* Wvp   = (const float*)d_in[7];
    const float* Wg    = (const float*)d_in[8];
    const float* bg    = (const float*)d_in[9];
    const float* Wu    = (const float*)d_in[10];
    const float* bu    = (const float*)d_in[11];
    const float* cn1_w = (const float*)d_in[12];
    const float* cn1_b = (const float*)d_in[13];
    const float* cn2_w = (const float*)d_in[14];
    const float* cn2_b = (const float*)d_in[15];
    const float* dn1_w = (const float*)d_in[16];
    const float* dn1_b = (const float*)d_in[17];
    const float* dn2_w = (const float*)d_in[18];
    const float* dn2_b = (const float*)d_in[19];
    const float* eps   = (const float*)d_in[20];
    float* out = (float*)d_out;

    prep_kernel<<<114, 256>>>(ln_w, ln_b, Wd, bd, Wq, Wk, Wvp, Wg,
                              cn1_w, cn1_b, cn2_w, cn2_b, dn1_w);
    fused_kernel<<<BPv, 256>>>(x, bg, Wu, bu, dn1_b, dn2_w, dn2_b, eps, out);
}

// round 4
// speedup vs baseline: 2.3135x; 1.1628x over previous
#include <cuda_runtime.h>
#include <cuda_bf16.h>
#include <math.h>

#define Bv 64
#define Cv 21
#define Pv 96
#define Dv 256
#define Rv 32
#define Hv 64
#define BPv (Bv*Pv)
#define PDv (Pv*Dv)
#define CRv (Cv*Rv)

// ---------------- device-global precomputed weights -------------------------
__device__ float g_Wd2[Dv*Rv];             // ln_w[d]*Wd[d][r], layout [d][r]
__device__ float g_W4[Rv*128];             // [kk][o]: o: 0-31 Wq, 32-63 Wk, 64-95 Wv, 96-127 Wg
__device__ __nv_bfloat16 g_dn1b[Hv*Dv];    // [j][d] = bf16(dn1_w[d][j])
__device__ __nv_bfloat16 g_dn2b[Hv*Dv];    // [j][d] = bf16(dn2_w[j][d])
__device__ float g_SW[Rv];                 // sum_d ln_w[d]*Wd[d][r]
__device__ float g_LB[Rv];                 // sum_d ln_b[d]*Wd[d][r] + bd[r]
__device__ float g_logits[Dv];             // channel logits (bp-invariant)

static __device__ __forceinline__ float geluf(float x) {
    return 0.5f * x * (1.0f + erff(x * 0.70710678118654752f));
}
static __device__ __forceinline__ float sigm(float x) {
    return 1.0f / (1.0f + expf(-x));
}
static __device__ __forceinline__ unsigned long long pk2(float a, float b) {
    unsigned long long r;
    asm("mov.b64 %0, {%1,%2};" : "=l"(r) : "f"(a), "f"(b));
    return r;
}
static __device__ __forceinline__ void ffma2(unsigned long long& d,
                                             unsigned long long a,
                                             unsigned long long b) {
    asm("fma.rn.f32x2 %0, %1, %2, %3;" : "=l"(d) : "l"(a), "l"(b), "l"(d));
}
static __device__ __forceinline__ float upksum(unsigned long long v) {
    float lo, hi;
    asm("mov.b64 {%0,%1}, %2;" : "=f"(lo), "=f"(hi) : "l"(v));
    return lo + hi;
}

// ---------------------------------------------------------------------------
// Prep: 178 blocks x 256 threads
// ---------------------------------------------------------------------------
__global__ void prep_kernel(const float* __restrict__ ln_w, const float* __restrict__ ln_b,
                            const float* __restrict__ Wd,   const float* __restrict__ bd,
                            const float* __restrict__ Wq,   const float* __restrict__ Wk,
                            const float* __restrict__ Wv,   const float* __restrict__ Wg,
                            const float* __restrict__ cn1_w, const float* __restrict__ cn1_b,
                            const float* __restrict__ cn2_w, const float* __restrict__ cn2_b,
                            const float* __restrict__ dn1_w, const float* __restrict__ dn2_w) {
    int bi = blockIdx.x, tid = threadIdx.x;
    if (bi < 32) {
        int idx = bi * 256 + tid;            // d*32+r
        g_Wd2[idx] = ln_w[idx >> 5] * Wd[idx];
    } else if (bi < 48) {
        int idx = (bi - 32) * 256 + tid;     // kk*128+o
        int kk = idx >> 7, o = idx & 127, m = o >> 5, r = o & 31;
        const float* src = (m == 0) ? Wq : (m == 1) ? Wk : (m == 2) ? Wv : Wg;
        g_W4[idx] = src[kk * Rv + r];
    } else if (bi < 112) {
        int j = bi - 48;
        g_dn1b[j * Dv + tid] = __float2bfloat16_rn(dn1_w[tid * Hv + j]);
    } else if (bi < 176) {
        int j = bi - 112;
        g_dn2b[j * Dv + tid] = __float2bfloat16_rn(dn2_w[j * Dv + tid]);
    } else if (bi == 176) {
        __shared__ float ssw[8][32], slb[8][32];
        int r = tid & 31, seg = tid >> 5;
        float sw = 0.f, lb = 0.f;
        for (int dd = 0; dd < 32; dd++) {
            int d = seg * 32 + dd;
            float wv = Wd[d * Rv + r];
            sw += ln_w[d] * wv;
            lb += ln_b[d] * wv;
        }
        ssw[seg][r] = sw; slb[seg][r] = lb;
        __syncthreads();
        if (tid < 32) {
            float a = 0.f, b2 = 0.f;
            #pragma unroll
            for (int s = 0; s < 8; s++) { a += ssw[s][tid]; b2 += slb[s][tid]; }
            g_SW[tid] = a;
            g_LB[tid] = b2 + bd[tid];
        }
    } else {
        __shared__ float hid[Hv];
        const float lc = logf(21.0f) / logf(1000.0f);
        if (tid < Hv) hid[tid] = geluf(lc * cn1_w[tid] + cn1_b[tid]);
        __syncthreads();
        float acc = cn2_b[tid];
        for (int j = 0; j < Hv; j++) acc += hid[j] * cn2_w[j * Dv + tid];
        g_logits[tid] = acc;
    }
}

// ---------------------------------------------------------------------------
// Fused kernel helpers
// ---------------------------------------------------------------------------
template<int NC>
static __device__ __forceinline__ void ph4_pass(const float* __restrict__ hrow0,
                                                int lane, int d0,
                                                float* __restrict__ dst) {
    unsigned long long acc[NC];
    #pragma unroll
    for (int j = 0; j < NC; j++) acc[j] = 0ull;
    #pragma unroll
    for (int i = 0; i < 8; i++) {
        int d = d0 + 4 * i;
        float w0 = __ldg(&g_Wd2[(d + 0) * Rv + lane]);
        float w1 = __ldg(&g_Wd2[(d + 1) * Rv + lane]);
        float w2 = __ldg(&g_Wd2[(d + 2) * Rv + lane]);
        float w3 = __ldg(&g_Wd2[(d + 3) * Rv + lane]);
        unsigned long long w01 = pk2(w0, w1), w23 = pk2(w2, w3);
        #pragma unroll
        for (int j = 0; j < NC; j++) {
            float4 h4 = *reinterpret_cast<const float4*>(hrow0 + j * Dv + d);
            ffma2(acc[j], pk2(h4.x, h4.y), w01);
            ffma2(acc[j], pk2(h4.z, h4.w), w23);
        }
    }
    #pragma unroll
    for (int j = 0; j < NC; j++) dst[j * Rv + lane] = upksum(acc[j]);
}

template<int NC>
static __device__ __forceinline__ void ph5_pass(const float* __restrict__ hl0,
                                                int o, float* __restrict__ val) {
    unsigned long long acc[NC];
    #pragma unroll
    for (int j = 0; j < NC; j++) acc[j] = 0ull;
    #pragma unroll
    for (int i = 0; i < 8; i++) {
        int kk = 4 * i;
        float w0 = __ldg(&g_W4[(kk + 0) * 128 + o]);
        float w1 = __ldg(&g_W4[(kk + 1) * 128 + o]);
        float w2 = __ldg(&g_W4[(kk + 2) * 128 + o]);
        float w3 = __ldg(&g_W4[(kk + 3) * 128 + o]);
        unsigned long long w01 = pk2(w0, w1), w23 = pk2(w2, w3);
        #pragma unroll
        for (int j = 0; j < NC; j++) {
            float4 h4 = *reinterpret_cast<const float4*>(hl0 + j * Rv + kk);
            ffma2(acc[j], pk2(h4.x, h4.y), w01);
            ffma2(acc[j], pk2(h4.z, h4.w), w23);
        }
    }
    #pragma unroll
    for (int j = 0; j < NC; j++) val[j] = upksum(acc[j]);
}

// ---------------------------------------------------------------------------
// Fully-fused kernel: one CTA per (b,p). 256 threads, 8 warps, 3 CTAs/SM.
// ---------------------------------------------------------------------------
__global__ __launch_bounds__(256, 3) void fused_kernel(
    const float* __restrict__ x,
    const float* __restrict__ bg,
    const float* __restrict__ Wu, const float* __restrict__ bu,
    const float* __restrict__ dn1_b,
    const float* __restrict__ dn2_b,
    const float* __restrict__ eps_p,
    float* __restrict__ out)
{
    __shared__ __align__(16) float h_s[Cv * Dv];     // raw tile
    __shared__ __align__(16) float sP[8 * CRv];      // split-K partials / QKVG
    __shared__ __align__(16) float hl_s[CRv];        // h_low, then A (=qn*gate)
    __shared__ __align__(16) float cv_s[Dv];         // channel variance
    __shared__ float mu_s[Cv], rs_s[Cv];
    __shared__ float gfp_s[8 * Rv];
    __shared__ float gf_s[Rv];
    __shared__ __align__(16) float hid_s[Hv];        // data-MLP hidden
    __shared__ float sred_s[2 * Dv];                 // gate GEMM2 partials
    __shared__ float gate_s[Dv];                     // final gate

    const int tid = threadIdx.x;
    const int lane = tid & 31;
    const int w = tid >> 5;
    const int bp = blockIdx.x;
    const int b = bp / Pv, p = bp % Pv;
    const int base = b * Cv * PDv + p * Dv + tid;

    // ---- phase 1: load tile + channel variance ---------------------------
    {
        float s1 = 0.f, s2 = 0.f;
        #pragma unroll
        for (int c = 0; c < Cv; c++) {
            float v = x[base + c * PDv];
            h_s[c * Dv + tid] = v;
            s1 += v; s2 += v * v;
        }
        cv_s[tid] = (s2 - s1 * s1 * (1.0f / 21.0f)) * (1.0f / 20.0f);
    }
    __syncthreads();

    // ---- phase 2: LN row stats -------------------------------------------
    #pragma unroll
    for (int ci = 0; ci < 3; ci++) {
        int c = w + 8 * ci;
        if (c < Cv) {
            float s = 0.f, ss = 0.f;
            #pragma unroll
            for (int k = 0; k < 8; k++) {
                float v = h_s[c * Dv + lane + 32 * k];
                s += v; ss += v * v;
            }
            #pragma unroll
            for (int o = 16; o > 0; o >>= 1) {
                s  += __shfl_xor_sync(0xffffffffu, s, o);
                ss += __shfl_xor_sync(0xffffffffu, ss, o);
            }
            if (lane == 0) {
                float mu = s * (1.0f / 256.0f);
                float var = ss * (1.0f / 256.0f) - mu * mu;
                mu_s[c] = mu;
                rs_s[c] = rsqrtf(var + 1e-5f);
            }
        }
    }

    // ---- phase 3: gate MLP GEMM1 (bf16 weights): hid = gelu(cv@dn1+b1) ---
    {
        // lane owns d-range [8*lane, 8*lane+8)
        float4 ca = *reinterpret_cast<const float4*>(&cv_s[8 * lane]);
        float4 cb = *reinterpret_cast<const float4*>(&cv_s[8 * lane + 4]);
        #pragma unroll
        for (int jj = 0; jj < 8; jj++) {
            int j = w * 8 + jj;
            uint4 wraw = __ldg(reinterpret_cast<const uint4*>(&g_dn1b[j * Dv + 8 * lane]));
            float2 f0 = __bfloat1622float2(*reinterpret_cast<__nv_bfloat162*>(&wraw.x));
            float2 f1 = __bfloat1622float2(*reinterpret_cast<__nv_bfloat162*>(&wraw.y));
            float2 f2 = __bfloat1622float2(*reinterpret_cast<__nv_bfloat162*>(&wraw.z));
            float2 f3 = __bfloat1622float2(*reinterpret_cast<__nv_bfloat162*>(&wraw.w));
            float part = ca.x * f0.x + ca.y * f0.y + ca.z * f1.x + ca.w * f1.y
                       + cb.x * f2.x + cb.y * f2.y + cb.z * f3.x + cb.w * f3.y;
            #pragma unroll
            for (int o = 16; o > 0; o >>= 1)
                part += __shfl_xor_sync(0xffffffffu, part, o);
            if (lane == 0) hid_s[j] = geluf(part + __ldg(&dn1_b[j]));
        }
    }

    // ---- phase 4: warp-split-K down-projection ---------------------------
    ph4_pass<11>(h_s,           lane, 32 * w, sP + (w * Cv +  0) * Rv);
    ph4_pass<10>(h_s + 11 * Dv, lane, 32 * w, sP + (w * Cv + 11) * Rv);
    __syncthreads();

    // ---- reduce partials + LN fold -> hl_s -------------------------------
    for (int idx = tid; idx < CRv; idx += 256) {
        int c = idx >> 5, r = idx & 31;
        float s = 0.f;
        #pragma unroll
        for (int w8 = 0; w8 < 8; w8++) s += sP[w8 * CRv + idx];
        hl_s[idx] = rs_s[c] * (s - mu_s[c] * __ldg(&g_SW[r])) + __ldg(&g_LB[r]);
    }

    // ---- gate MLP GEMM2 partials (bf16, d-pair per thread) ---------------
    {
        const int dp = tid & 127;         // d-pair: d = 2dp, 2dp+1
        const int jh = tid >> 7;          // j-half: j in [32jh, 32jh+32)
        float a0 = 0.f, a1 = 0.f;
        #pragma unroll 4
        for (int j4 = 0; j4 < 8; j4++) {
            int j = 32 * jh + 4 * j4;
            float4 h4 = *reinterpret_cast<const float4*>(&hid_s[j]);
            float2 w0 = __bfloat1622float2(
                __ldg(reinterpret_cast<const __nv_bfloat162*>(g_dn2b + (j + 0) * Dv) + dp));
            float2 w1 = __bfloat1622float2(
                __ldg(reinterpret_cast<const __nv_bfloat162*>(g_dn2b + (j + 1) * Dv) + dp));
            float2 w2 = __bfloat1622float2(
                __ldg(reinterpret_cast<const __nv_bfloat162*>(g_dn2b + (j + 2) * Dv) + dp));
            float2 w3 = __bfloat1622float2(
                __ldg(reinterpret_cast<const __nv_bfloat162*>(g_dn2b + (j + 3) * Dv) + dp));
            a0 = fmaf(h4.x, w0.x, fmaf(h4.y, w1.x, fmaf(h4.z, w2.x, fmaf(h4.w, w3.x, a0))));
            a1 = fmaf(h4.x, w0.y, fmaf(h4.y, w1.y, fmaf(h4.z, w2.y, fmaf(h4.w, w3.y, a1))));
        }
        sred_s[jh * Dv + 2 * dp]     = a0;
        sred_s[jh * Dv + 2 * dp + 1] = a1;
    }
    __syncthreads();

    // ---- finalize gate ----------------------------------------------------
    {
        float dc = sred_s[tid] + sred_s[Dv + tid];
        float ev = __ldg(eps_p);
        gate_s[tid] = sigm(__ldg(&g_logits[tid]) + ev * (dc + __ldg(&dn2_b[tid])));
    }

    // ---- phase 5: stacked QKVG -------------------------------------------
    {
        const int o = tid & 127, grp = tid >> 7;
        const int m = o >> 5, r = o & 31;
        const int nc = grp ? 10 : 11;
        float val[11];
        if (grp == 0) ph5_pass<11>(hl_s, o, val);
        else          ph5_pass<10>(hl_s + 11 * Rv, o, val);

        float* dst = sP + m * CRv + (grp * 11) * Rv;
        if (m < 2) {
            #pragma unroll
            for (int j = 0; j < 11; j++) if (j < nc) {
                float q = val[j];
                float qs = q * q;
                #pragma unroll
                for (int off = 16; off > 0; off >>= 1)
                    qs += __shfl_xor_sync(0xffffffffu, qs, off);
                dst[j * Rv + r] = q / fmaxf(sqrtf(qs), 1e-12f);
            }
        } else if (m == 2) {
            #pragma unroll
            for (int j = 0; j < 11; j++) if (j < nc)
                dst[j * Rv + r] = val[j];
        } else {
            float bgr = __ldg(&bg[r]);
            #pragma unroll
            for (int j = 0; j < 11; j++) if (j < nc)
                dst[j * Rv + r] = sigm(val[j] + bgr);
        }
    }
    __syncthreads();

    // ---- combine: A = qn*gate into hl_s; gf partials ---------------------
    {
        const int r2 = tid & 31, cg = tid >> 5;
        float gfp = 0.f;
        #pragma unroll
        for (int ci = 0; ci < 3; ci++) {
            int c = cg + 8 * ci;
            if (c < Cv) {
                float qn = sP[0 * CRv + c * Rv + r2];
                float gs = sP[3 * CRv + c * Rv + r2];
                hl_s[c * Rv + r2] = qn * gs;
                gfp += sP[1 * CRv + c * Rv + r2] * sP[2 * CRv + c * Rv + r2];
            }
        }
        gfp_s[cg * Rv + r2] = gfp;
    }
    __syncthreads();
    if (tid < Rv) {
        float s = 0.f;
        #pragma unroll
        for (int cg = 0; cg < 8; cg++) s += gfp_s[cg * Rv + tid];
        gf_s[tid] = s;
    }
    __syncthreads();

    // ---- phase 6: mixed = A @ (Wu*gf) + bu; out = h + gate*mixed ---------
    {
        unsigned long long wf[16];
        #pragma unroll
        for (int r2 = 0; r2 < 16; r2++) {
            float wa = __ldg(&Wu[(2 * r2 + 0) * Dv + tid]) * gf_s[2 * r2 + 0];
            float wb = __ldg(&Wu[(2 * r2 + 1) * Dv + tid]) * gf_s[2 * r2 + 1];
            wf[r2] = pk2(wa, wb);
        }
        const float buv = __ldg(&bu[tid]);
        const float gv = gate_s[tid];
        #pragma unroll
        for (int c = 0; c < Cv; c++) {
            const float4* ar = reinterpret_cast<const float4*>(&hl_s[c * Rv]);
            unsigned long long acc0 = 0ull, acc1 = 0ull;
            #pragma unroll
            for (int r4 = 0; r4 < 4; r4++) {
                float4 a4 = ar[2 * r4];
                float4 b4 = ar[2 * r4 + 1];
                ffma2(acc0, pk2(a4.x, a4.y), wf[4 * r4 + 0]);
                ffma2(acc1, pk2(a4.z, a4.w), wf[4 * r4 + 1]);
                ffma2(acc0, pk2(b4.x, b4.y), wf[4 * r4 + 2]);
                ffma2(acc1, pk2(b4.z, b4.w), wf[4 * r4 + 3]);
            }
            float mixed = upksum(acc0) + upksum(acc1) + buv;
            out[base + c * PDv] = h_s[c * Dv + tid] + gv * mixed;
        }
    }
}

// ---------------------------------------------------------------------------
extern "C" void kernel_launch(void* const* d_in, const int* in_sizes, int n_in,
                              void* d_out, int out_size) {
    const float* x     = (const float*)d_in[0];
    const float* ln_w  = (const float*)d_in[1];
    const float* ln_b  = (const float*)d_in[2];
    const float* Wd    = (const float*)d_in[3];
    const float* bd    = (const float*)d_in[4];
    const float* Wq    = (const float*)d_in[5];
    const float* Wk    = (const float*)d_in[6];
    const float* Wvp   = (const float*)d_in[7];
    const float* Wg    = (const float*)d_in[8];
    const float* bg    = (const float*)d_in[9];
    const float* Wu    = (const float*)d_in[10];
    const float* bu    = (const float*)d_in[11];
    const float* cn1_w = (const float*)d_in[12];
    const float* cn1_b = (const float*)d_in[13];
    const float* cn2_w = (const float*)d_in[14];
    const float* cn2_b = (const float*)d_in[15];
    const float* dn1_w = (const float*)d_in[16];
    const float* dn1_b = (const float*)d_in[17];
    const float* dn2_w = (const float*)d_in[18];
    const float* dn2_b = (const float*)d_in[19];
    const float* eps   = (const float*)d_in[20];
    float* out = (float*)d_out;

    prep_kernel<<<178, 256>>>(ln_w, ln_b, Wd, bd, Wq, Wk, Wvp, Wg,
                              cn1_w, cn1_b, cn2_w, cn2_b, dn1_w, dn2_w);
    fused_kernel<<<BPv, 256>>>(x, bg, Wu, bu, dn1_b, dn2_b, eps, out);
}

// round 5
// speedup vs baseline: 2.4947x; 1.0783x over previous
#include <cuda_runtime.h>
#include <cuda_bf16.h>
#include <math.h>

#define Bv 64
#define Cv 21
#define Pv 96
#define Dv 256
#define Rv 32
#define Hv 64
#define BPv (Bv*Pv)
#define PDv (Pv*Dv)
#define CRv (Cv*Rv)

// ---------------- device-global precomputed weights -------------------------
__device__ __nv_bfloat162 g_Wd2b[(Dv/2)*Rv];   // [(d/2)*32+r] = (lnw*Wd[d][r], lnw*Wd[d+1][r])
__device__ __nv_bfloat162 g_W4b[(Rv/2)*128];   // [(kk/2)*128+o] = (W4[kk][o], W4[kk+1][o])
__device__ __nv_bfloat162 g_Wub[(Rv/2)*Dv];    // [(r/2)*256+d] = (Wu[r][d], Wu[r+1][d])
__device__ __nv_bfloat16  g_dn1b[Hv*Dv];       // [j][d] = bf16(dn1_w[d][j])
__device__ __nv_bfloat16  g_dn2b[Hv*Dv];       // [j][d] = bf16(dn2_w[j][d])
__device__ float g_SW[Rv];                     // sum_d ln_w[d]*Wd[d][r]
__device__ float g_LB[Rv];                     // sum_d ln_b[d]*Wd[d][r] + bd[r]
__device__ float g_logits[Dv];                 // channel logits (bp-invariant)

static __device__ __forceinline__ float geluf(float x) {
    return 0.5f * x * (1.0f + erff(x * 0.70710678118654752f));
}
static __device__ __forceinline__ float sigm(float x) {
    return 1.0f / (1.0f + expf(-x));
}
static __device__ __forceinline__ unsigned long long pk2(float a, float b) {
    unsigned long long r;
    asm("mov.b64 %0, {%1,%2};" : "=l"(r) : "f"(a), "f"(b));
    return r;
}
static __device__ __forceinline__ void ffma2(unsigned long long& d,
                                             unsigned long long a,
                                             unsigned long long b) {
    asm("fma.rn.f32x2 %0, %1, %2, %3;" : "=l"(d) : "l"(a), "l"(b), "l"(d));
}
static __device__ __forceinline__ float upksum(unsigned long long v) {
    float lo, hi;
    asm("mov.b64 {%0,%1}, %2;" : "=f"(lo), "=f"(hi) : "l"(v));
    return lo + hi;
}
static __device__ __forceinline__ unsigned long long bf2f2pk(__nv_bfloat162 b) {
    float2 f = __bfloat1622float2(b);
    return pk2(f.x, f.y);
}

// ---------------------------------------------------------------------------
// Prep: 170 blocks x 256 threads
// ---------------------------------------------------------------------------
__global__ void prep_kernel(const float* __restrict__ ln_w, const float* __restrict__ ln_b,
                            const float* __restrict__ Wd,   const float* __restrict__ bd,
                            const float* __restrict__ Wq,   const float* __restrict__ Wk,
                            const float* __restrict__ Wv,   const float* __restrict__ Wg,
                            const float* __restrict__ Wu,
                            const float* __restrict__ cn1_w, const float* __restrict__ cn1_b,
                            const float* __restrict__ cn2_w, const float* __restrict__ cn2_b,
                            const float* __restrict__ dn1_w, const float* __restrict__ dn2_w) {
    int bi = blockIdx.x, tid = threadIdx.x;
    if (bi < 16) {
        int idx = bi * 256 + tid;             // (d/2)*32 + r
        int dp = idx >> 5, r = idx & 31, d = 2 * dp;
        float a = ln_w[d]     * Wd[d * Rv + r];
        float b = ln_w[d + 1] * Wd[(d + 1) * Rv + r];
        g_Wd2b[idx] = __floats2bfloat162_rn(a, b);
    } else if (bi < 24) {
        int idx = (bi - 16) * 256 + tid;      // (kk/2)*128 + o
        int kp = idx >> 7, o = idx & 127, kk = 2 * kp;
        int m = o >> 5, r = o & 31;
        const float* src = (m == 0) ? Wq : (m == 1) ? Wk : (m == 2) ? Wv : Wg;
        g_W4b[idx] = __floats2bfloat162_rn(src[kk * Rv + r], src[(kk + 1) * Rv + r]);
    } else if (bi < 40) {
        int idx = (bi - 24) * 256 + tid;      // (r/2)*256 + d
        int rp = idx >> 8, d = idx & 255;
        g_Wub[idx] = __floats2bfloat162_rn(Wu[(2 * rp) * Dv + d], Wu[(2 * rp + 1) * Dv + d]);
    } else if (bi < 104) {
        int j = bi - 40;
        g_dn1b[j * Dv + tid] = __float2bfloat16_rn(dn1_w[tid * Hv + j]);
    } else if (bi < 168) {
        int j = bi - 104;
        g_dn2b[j * Dv + tid] = __float2bfloat16_rn(dn2_w[j * Dv + tid]);
    } else if (bi == 168) {
        __shared__ float ssw[8][32], slb[8][32];
        int r = tid & 31, seg = tid >> 5;
        float sw = 0.f, lb = 0.f;
        for (int dd = 0; dd < 32; dd++) {
            int d = seg * 32 + dd;
            float wv = Wd[d * Rv + r];
            sw += ln_w[d] * wv;
            lb += ln_b[d] * wv;
        }
        ssw[seg][r] = sw; slb[seg][r] = lb;
        __syncthreads();
        if (tid < 32) {
            float a = 0.f, b2 = 0.f;
            #pragma unroll
            for (int s = 0; s < 8; s++) { a += ssw[s][tid]; b2 += slb[s][tid]; }
            g_SW[tid] = a;
            g_LB[tid] = b2 + bd[tid];
        }
    } else {
        __shared__ float hid[Hv];
        const float lc = logf(21.0f) / logf(1000.0f);
        if (tid < Hv) hid[tid] = geluf(lc * cn1_w[tid] + cn1_b[tid]);
        __syncthreads();
        float acc = cn2_b[tid];
        for (int j = 0; j < Hv; j++) acc += hid[j] * cn2_w[j * Dv + tid];
        g_logits[tid] = acc;
    }
}

// ---------------------------------------------------------------------------
// Phase-4 split-K pass: warp handles d-chunk [d0, d0+32) for NC channels.
// Weights bf16-paired; h fp32 broadcast; partials written bf16.
// ---------------------------------------------------------------------------
template<int NC>
static __device__ __forceinline__ void ph4_pass(const float* __restrict__ hrow0,
                                                int lane, int d0,
                                                __nv_bfloat16* __restrict__ dst) {
    unsigned long long acc[NC];
    #pragma unroll
    for (int j = 0; j < NC; j++) acc[j] = 0ull;
    #pragma unroll
    for (int i = 0; i < 8; i++) {
        int d = d0 + 4 * i;
        unsigned long long w01 = bf2f2pk(__ldg(&g_Wd2b[(d >> 1) * Rv + lane]));
        unsigned long long w23 = bf2f2pk(__ldg(&g_Wd2b[((d >> 1) + 1) * Rv + lane]));
        #pragma unroll
        for (int j = 0; j < NC; j++) {
            float4 h4 = *reinterpret_cast<const float4*>(hrow0 + j * Dv + d);
            ffma2(acc[j], pk2(h4.x, h4.y), w01);
            ffma2(acc[j], pk2(h4.z, h4.w), w23);
        }
    }
    #pragma unroll
    for (int j = 0; j < NC; j++) dst[j * Rv + lane] = __float2bfloat16_rn(upksum(acc[j]));
}

// ---------------------------------------------------------------------------
// Fully-fused kernel: one CTA per (b,p). 256 threads, 8 warps, 3 CTAs/SM.
// ---------------------------------------------------------------------------
__global__ __launch_bounds__(256, 3) void fused_kernel(
    const float* __restrict__ x,
    const float* __restrict__ bg,
    const float* __restrict__ bu,
    const float* __restrict__ dn1_b,
    const float* __restrict__ dn2_b,
    const float* __restrict__ eps_p,
    float* __restrict__ out)
{
    __shared__ __align__(16) float h_s[Cv * Dv];            // raw tile
    __shared__ __align__(16) __nv_bfloat16 sPb[8 * CRv];    // split-K partials (bf16)
    __shared__ __align__(16) float hl_s[CRv];               // h_low
    __shared__ __align__(16) float A_s[CRv];                // qn * gate
    __shared__ __align__(16) float cv_s[Dv];                // channel variance
    __shared__ float mu_s[Cv], rs_s[Cv];
    __shared__ float gfp_s[4 * Rv];
    __shared__ float gf_s[Rv];
    __shared__ __align__(16) float hid_s[Hv];               // data-MLP hidden
    __shared__ float sred_s[2 * Dv];                        // gate GEMM2 partials
    __shared__ float gate_s[Dv];                            // final gate

    const int tid = threadIdx.x;
    const int lane = tid & 31;
    const int w = tid >> 5;
    const int bp = blockIdx.x;
    const int b = bp / Pv, p = bp % Pv;
    const int base = b * Cv * PDv + p * Dv + tid;

    // ---- phase 1: load tile + channel variance ---------------------------
    {
        float s1 = 0.f, s2 = 0.f;
        #pragma unroll
        for (int c = 0; c < Cv; c++) {
            float v = x[base + c * PDv];
            h_s[c * Dv + tid] = v;
            s1 += v; s2 += v * v;
        }
        cv_s[tid] = (s2 - s1 * s1 * (1.0f / 21.0f)) * (1.0f / 20.0f);
    }
    __syncthreads();

    // ---- phase 2: LN row stats (warp w owns rows w, w+8, w+16) -----------
    #pragma unroll
    for (int ci = 0; ci < 3; ci++) {
        int c = w + 8 * ci;
        if (c < Cv) {
            float s = 0.f, ss = 0.f;
            #pragma unroll
            for (int k = 0; k < 8; k++) {
                float v = h_s[c * Dv + lane + 32 * k];
                s += v; ss += v * v;
            }
            #pragma unroll
            for (int o = 16; o > 0; o >>= 1) {
                s  += __shfl_xor_sync(0xffffffffu, s, o);
                ss += __shfl_xor_sync(0xffffffffu, ss, o);
            }
            if (lane == 0) {
                float mu = s * (1.0f / 256.0f);
                float var = ss * (1.0f / 256.0f) - mu * mu;
                mu_s[c] = mu;
                rs_s[c] = rsqrtf(var + 1e-5f);
            }
        }
    }

    // ---- phase 3: gate MLP GEMM1 (bf16): hid = gelu(cv @ dn1 + b1) -------
    {
        float4 ca = *reinterpret_cast<const float4*>(&cv_s[8 * lane]);
        float4 cb = *reinterpret_cast<const float4*>(&cv_s[8 * lane + 4]);
        #pragma unroll
        for (int jj = 0; jj < 8; jj++) {
            int j = w * 8 + jj;
            uint4 wraw = __ldg(reinterpret_cast<const uint4*>(&g_dn1b[j * Dv + 8 * lane]));
            float2 f0 = __bfloat1622float2(*reinterpret_cast<__nv_bfloat162*>(&wraw.x));
            float2 f1 = __bfloat1622float2(*reinterpret_cast<__nv_bfloat162*>(&wraw.y));
            float2 f2 = __bfloat1622float2(*reinterpret_cast<__nv_bfloat162*>(&wraw.z));
            float2 f3 = __bfloat1622float2(*reinterpret_cast<__nv_bfloat162*>(&wraw.w));
            float part = ca.x * f0.x + ca.y * f0.y + ca.z * f1.x + ca.w * f1.y
                       + cb.x * f2.x + cb.y * f2.y + cb.z * f3.x + cb.w * f3.y;
            #pragma unroll
            for (int o = 16; o > 0; o >>= 1)
                part += __shfl_xor_sync(0xffffffffu, part, o);
            if (lane == 0) hid_s[j] = geluf(part + __ldg(&dn1_b[j]));
        }
    }

    // ---- phase 4: warp-split-K down-projection (bf16 weights) ------------
    ph4_pass<11>(h_s,           lane, 32 * w, sPb + (w * Cv +  0) * Rv);
    ph4_pass<10>(h_s + 11 * Dv, lane, 32 * w, sPb + (w * Cv + 11) * Rv);
    __syncthreads();

    // ---- reduce partials + LN fold -> hl_s (fp32) ------------------------
    for (int idx = tid; idx < CRv; idx += 256) {
        int c = idx >> 5, r = idx & 31;
        float s = 0.f;
        #pragma unroll
        for (int w8 = 0; w8 < 8; w8++) s += __bfloat162float(sPb[w8 * CRv + idx]);
        hl_s[idx] = rs_s[c] * (s - mu_s[c] * __ldg(&g_SW[r])) + __ldg(&g_LB[r]);
    }

    // ---- gate MLP GEMM2 partials (bf16, d-pair per thread) ---------------
    {
        const int dp = tid & 127;         // d-pair: d = 2dp, 2dp+1
        const int jh = tid >> 7;          // j-half
        float a0 = 0.f, a1 = 0.f;
        #pragma unroll 4
        for (int j4 = 0; j4 < 8; j4++) {
            int j = 32 * jh + 4 * j4;
            float4 h4 = *reinterpret_cast<const float4*>(&hid_s[j]);
            float2 w0 = __bfloat1622float2(
                __ldg(reinterpret_cast<const __nv_bfloat162*>(g_dn2b + (j + 0) * Dv) + dp));
            float2 w1 = __bfloat1622float2(
                __ldg(reinterpret_cast<const __nv_bfloat162*>(g_dn2b + (j + 1) * Dv) + dp));
            float2 w2 = __bfloat1622float2(
                __ldg(reinterpret_cast<const __nv_bfloat162*>(g_dn2b + (j + 2) * Dv) + dp));
            float2 w3 = __bfloat1622float2(
                __ldg(reinterpret_cast<const __nv_bfloat162*>(g_dn2b + (j + 3) * Dv) + dp));
            a0 = fmaf(h4.x, w0.x, fmaf(h4.y, w1.x, fmaf(h4.z, w2.x, fmaf(h4.w, w3.x, a0))));
            a1 = fmaf(h4.x, w0.y, fmaf(h4.y, w1.y, fmaf(h4.z, w2.y, fmaf(h4.w, w3.y, a1))));
        }
        sred_s[jh * Dv + 2 * dp]     = a0;
        sred_s[jh * Dv + 2 * dp + 1] = a1;
    }
    __syncthreads();   // hl_s + sred ready

    // ---- finalize gate ----------------------------------------------------
    {
        float dc = sred_s[tid] + sred_s[Dv + tid];
        float ev = __ldg(eps_p);
        gate_s[tid] = sigm(__ldg(&g_logits[tid]) + ev * (dc + __ldg(&dn2_b[tid])));
    }

    // ---- phase 5: role-paired QKVG. warp = (role, cgrp); lane = r --------
    {
        const int r = lane;
        const int role = w & 1;                      // 0: q&g, 1: k&v
        const int cgrp = w >> 1;                     // 0..3
        const int cstart = (cgrp == 0) ? 0 : (5 * cgrp + 1);
        const int ccnt   = (cgrp == 0) ? 6 : 5;
        const int o1 = role ? (32 + r) : r;          // k | q
        const int o2 = role ? (64 + r) : (96 + r);   // v | g

        float acc1[6], acc2[6];
        #pragma unroll
        for (int j = 0; j < 6; j++) { acc1[j] = 0.f; acc2[j] = 0.f; }

        #pragma unroll
        for (int pass = 0; pass < 2; pass++) {
            const int kk0 = 16 * pass;
            unsigned long long w1[8], w2[8];
            #pragma unroll
            for (int t = 0; t < 8; t++) {
                int kp = (kk0 >> 1) + t;
                w1[t] = bf2f2pk(__ldg(&g_W4b[kp * 128 + o1]));
                w2[t] = bf2f2pk(__ldg(&g_W4b[kp * 128 + o2]));
            }
            #pragma unroll
            for (int j = 0; j < 6; j++) {
                if (j < ccnt) {
                    const float* hr = hl_s + (cstart + j) * Rv + kk0;
                    unsigned long long a1p = 0ull, a2p = 0ull;
                    #pragma unroll
                    for (int q4 = 0; q4 < 4; q4++) {
                        float4 h4 = *reinterpret_cast<const float4*>(hr + 4 * q4);
                        unsigned long long hx = pk2(h4.x, h4.y), hy = pk2(h4.z, h4.w);
                        ffma2(a1p, hx, w1[2 * q4]); ffma2(a1p, hy, w1[2 * q4 + 1]);
                        ffma2(a2p, hx, w2[2 * q4]); ffma2(a2p, hy, w2[2 * q4 + 1]);
                    }
                    acc1[j] += upksum(a1p);
                    acc2[j] += upksum(a2p);
                }
            }
        }

        if (role == 0) {
            float bgr = __ldg(&bg[r]);
            #pragma unroll
            for (int j = 0; j < 6; j++) {
                if (j < ccnt) {
                    float q = acc1[j];
                    float qs = q * q;
                    #pragma unroll
                    for (int o = 16; o > 0; o >>= 1)
                        qs += __shfl_xor_sync(0xffffffffu, qs, o);
                    float qn = q / fmaxf(sqrtf(qs), 1e-12f);
                    A_s[(cstart + j) * Rv + r] = qn * sigm(acc2[j] + bgr);
                }
            }
        } else {
            float gfp = 0.f;
            #pragma unroll
            for (int j = 0; j < 6; j++) {
                if (j < ccnt) {
                    float k = acc1[j];
                    float ks = k * k;
                    #pragma unroll
                    for (int o = 16; o > 0; o >>= 1)
                        ks += __shfl_xor_sync(0xffffffffu, ks, o);
                    float kn = k / fmaxf(sqrtf(ks), 1e-12f);
                    gfp += kn * acc2[j];
                }
            }
            gfp_s[cgrp * Rv + r] = gfp;
        }
    }
    __syncthreads();   // A_s, gfp_s, gate_s ready

    if (tid < Rv) {
        gf_s[tid] = gfp_s[tid] + gfp_s[Rv + tid] + gfp_s[2 * Rv + tid] + gfp_s[3 * Rv + tid];
    }
    __syncthreads();

    // ---- phase 6: mixed = A @ (Wu*gf) + bu; out = h + gate*mixed ---------
    {
        unsigned long long wf[16];
        #pragma unroll
        for (int t = 0; t < 16; t++) {
            float2 f = __bfloat1622float2(__ldg(&g_Wub[t * Dv + tid]));
            wf[t] = pk2(f.x * gf_s[2 * t], f.y * gf_s[2 * t + 1]);
        }
        const float buv = __ldg(&bu[tid]);
        const float gv = gate_s[tid];
        #pragma unroll
        for (int c = 0; c < Cv; c++) {
            const float4* ar = reinterpret_cast<const float4*>(&A_s[c * Rv]);
            unsigned long long acc0 = 0ull, acc1 = 0ull;
            #pragma unroll
            for (int r4 = 0; r4 < 4; r4++) {
                float4 a4 = ar[2 * r4];
                float4 b4 = ar[2 * r4 + 1];
                ffma2(acc0, pk2(a4.x, a4.y), wf[4 * r4 + 0]);
                ffma2(acc1, pk2(a4.z, a4.w), wf[4 * r4 + 1]);
                ffma2(acc0, pk2(b4.x, b4.y), wf[4 * r4 + 2]);
                ffma2(acc1, pk2(b4.z, b4.w), wf[4 * r4 + 3]);
            }
            float mixed = upksum(acc0) + upksum(acc1) + buv;
            out[base + c * PDv] = h_s[c * Dv + tid] + gv * mixed;
        }
    }
}

// ---------------------------------------------------------------------------
extern "C" void kernel_launch(void* const* d_in, const int* in_sizes, int n_in,
                              void* d_out, int out_size) {
    const float* x     = (const float*)d_in[0];
    const float* ln_w  = (const float*)d_in[1];
    const float* ln_b  = (const float*)d_in[2];
    const float* Wd    = (const float*)d_in[3];
    const float* bd    = (const float*)d_in[4];
    const float* Wq    = (const float*)d_in[5];
    const float* Wk    = (const float*)d_in[6];
    const float* Wvp   = (const float*)d_in[7];
    const float* Wg    = (const float*)d_in[8];
    const float* bg    = (const float*)d_in[9];
    const float* Wu    = (const float*)d_in[10];
    const float* bu    = (const float*)d_in[11];
    const float* cn1_w = (const float*)d_in[12];
    const float* cn1_b = (const float*)d_in[13];
    const float* cn2_w = (const float*)d_in[14];
    const float* cn2_b = (const float*)d_in[15];
    const float* dn1_w = (const float*)d_in[16];
    const float* dn1_b = (const float*)d_in[17];
    const float* dn2_w = (const float*)d_in[18];
    const float* dn2_b = (const float*)d_in[19];
    const float* eps   = (const float*)d_in[20];
    float* out = (float*)d_out;

    prep_kernel<<<170, 256>>>(ln_w, ln_b, Wd, bd, Wq, Wk, Wvp, Wg, Wu,
                              cn1_w, cn1_b, cn2_w, cn2_b, dn1_w, dn2_w);
    fused_kernel<<<BPv, 256>>>(x, bg, bu, dn1_b, dn2_b, eps, out);
}

// round 6
// speedup vs baseline: 2.9022x; 1.1634x over previous
#include <cuda_runtime.h>
#include <cuda_bf16.h>
#include <math.h>

#define Bv 64
#define Cv 21
#define Pv 96
#define Dv 256
#define Rv 32
#define Hv 64
#define BPv (Bv*Pv)
#define PDv (Pv*Dv)
#define CRv (Cv*Rv)

// padded smem strides (elements), all rows 16B-aligned & ldsm bank-rotated
#define HB  264   // h_b / wu_b row stride (528B = 33*16)
#define WB  40    // wd_b row stride (80B = 5*16)
#define AB  40    // A_b row stride

// ---------------- device-global precomputed weights -------------------------
__device__ __nv_bfloat16  g_Wdh[Dv*Rv];       // [d][r] = bf16(ln_w[d]*Wd[d][r])
__device__ __nv_bfloat162 g_W4b[(Rv/2)*128];  // [(kk/2)*128+o] (phase5)
__device__ __nv_bfloat16  g_Wuh[Rv*Dv];       // [r][d] = bf16(Wu[r][d])
__device__ __nv_bfloat16  g_dn1b[Hv*Dv];      // [j][d] = bf16(dn1_w[d][j])
__device__ __nv_bfloat16  g_dn2b[Hv*Dv];      // [j][d] = bf16(dn2_w[j][d])
__device__ float g_SW[Rv];
__device__ float g_LB[Rv];
__device__ float g_logits[Dv];

static __device__ __forceinline__ float geluf(float x) {
    return 0.5f * x * (1.0f + erff(x * 0.70710678118654752f));
}
static __device__ __forceinline__ float sigm(float x) {
    return 1.0f / (1.0f + expf(-x));
}
static __device__ __forceinline__ unsigned long long pk2(float a, float b) {
    unsigned long long r;
    asm("mov.b64 %0, {%1,%2};" : "=l"(r) : "f"(a), "f"(b));
    return r;
}
static __device__ __forceinline__ void ffma2(unsigned long long& d,
                                             unsigned long long a,
                                             unsigned long long b) {
    asm("fma.rn.f32x2 %0, %1, %2, %3;" : "=l"(d) : "l"(a), "l"(b), "l"(d));
}
static __device__ __forceinline__ float upksum(unsigned long long v) {
    float lo, hi;
    asm("mov.b64 {%0,%1}, %2;" : "=f"(lo), "=f"(hi) : "l"(v));
    return lo + hi;
}
static __device__ __forceinline__ unsigned long long bf2f2pk(__nv_bfloat162 b) {
    float2 f = __bfloat1622float2(b);
    return pk2(f.x, f.y);
}
static __device__ __forceinline__ unsigned smem_u32(const void* p) {
    return (unsigned)__cvta_generic_to_shared(p);
}
static __device__ __forceinline__ void ldsm_x4(unsigned& r0, unsigned& r1,
                                               unsigned& r2, unsigned& r3, unsigned a) {
    asm volatile("ldmatrix.sync.aligned.m8n8.x4.shared.b16 {%0,%1,%2,%3}, [%4];"
                 : "=r"(r0), "=r"(r1), "=r"(r2), "=r"(r3) : "r"(a));
}
static __device__ __forceinline__ void ldsm_x2t(unsigned& r0, unsigned& r1, unsigned a) {
    asm volatile("ldmatrix.sync.aligned.m8n8.x2.trans.shared.b16 {%0,%1}, [%2];"
                 : "=r"(r0), "=r"(r1) : "r"(a));
}
static __device__ __forceinline__ void mma16816(float& c0, float& c1, float& c2, float& c3,
                                                unsigned a0, unsigned a1, unsigned a2, unsigned a3,
                                                unsigned b0, unsigned b1) {
    asm volatile("mma.sync.aligned.m16n8k16.row.col.f32.bf16.bf16.f32 "
                 "{%0,%1,%2,%3}, {%4,%5,%6,%7}, {%8,%9}, {%0,%1,%2,%3};"
                 : "+f"(c0), "+f"(c1), "+f"(c2), "+f"(c3)
                 : "r"(a0), "r"(a1), "r"(a2), "r"(a3), "r"(b0), "r"(b1));
}

// ---------------------------------------------------------------------------
// Prep: 202 blocks x 256 threads
// ---------------------------------------------------------------------------
__global__ void prep_kernel(const float* __restrict__ ln_w, const float* __restrict__ ln_b,
                            const float* __restrict__ Wd,   const float* __restrict__ bd,
                            const float* __restrict__ Wq,   const float* __restrict__ Wk,
                            const float* __restrict__ Wv,   const float* __restrict__ Wg,
                            const float* __restrict__ Wu,
                            const float* __restrict__ cn1_w, const float* __restrict__ cn1_b,
                            const float* __restrict__ cn2_w, const float* __restrict__ cn2_b,
                            const float* __restrict__ dn1_w, const float* __restrict__ dn2_w) {
    int bi = blockIdx.x, tid = threadIdx.x;
    if (bi < 32) {
        int idx = bi * 256 + tid;            // d*32 + r
        g_Wdh[idx] = __float2bfloat16_rn(ln_w[idx >> 5] * Wd[idx]);
    } else if (bi < 40) {
        int idx = (bi - 32) * 256 + tid;     // (kk/2)*128 + o
        int kp = idx >> 7, o = idx & 127, kk = 2 * kp;
        int m = o >> 5, r = o & 31;
        const float* src = (m == 0) ? Wq : (m == 1) ? Wk : (m == 2) ? Wv : Wg;
        g_W4b[idx] = __floats2bfloat162_rn(src[kk * Rv + r], src[(kk + 1) * Rv + r]);
    } else if (bi < 72) {
        int idx = (bi - 40) * 256 + tid;     // r*256 + d
        g_Wuh[idx] = __float2bfloat16_rn(Wu[idx]);
    } else if (bi < 136) {
        int j = bi - 72;
        g_dn1b[j * Dv + tid] = __float2bfloat16_rn(dn1_w[tid * Hv + j]);
    } else if (bi < 200) {
        int j = bi - 136;
        g_dn2b[j * Dv + tid] = __float2bfloat16_rn(dn2_w[j * Dv + tid]);
    } else if (bi == 200) {
        __shared__ float ssw[8][32], slb[8][32];
        int r = tid & 31, seg = tid >> 5;
        float sw = 0.f, lb = 0.f;
        for (int dd = 0; dd < 32; dd++) {
            int d = seg * 32 + dd;
            float wv = Wd[d * Rv + r];
            sw += ln_w[d] * wv;
            lb += ln_b[d] * wv;
        }
        ssw[seg][r] = sw; slb[seg][r] = lb;
        __syncthreads();
        if (tid < 32) {
            float a = 0.f, b2 = 0.f;
            #pragma unroll
            for (int s = 0; s < 8; s++) { a += ssw[s][tid]; b2 += slb[s][tid]; }
            g_SW[tid] = a;
            g_LB[tid] = b2 + bd[tid];
        }
    } else {
        __shared__ float hid[Hv];
        const float lc = logf(21.0f) / logf(1000.0f);
        if (tid < Hv) hid[tid] = geluf(lc * cn1_w[tid] + cn1_b[tid]);
        __syncthreads();
        float acc = cn2_b[tid];
        for (int j = 0; j < Hv; j++) acc += hid[j] * cn2_w[j * Dv + tid];
        g_logits[tid] = acc;
    }
}

// ---------------------------------------------------------------------------
// Fully-fused kernel (tensor-core GEMMs): one CTA per (b,p). 256 thr, 8 warps.
// ---------------------------------------------------------------------------
__global__ __launch_bounds__(256, 3) void fused_kernel(
    const float* __restrict__ x,
    const float* __restrict__ bg,
    const float* __restrict__ bu,
    const float* __restrict__ dn1_b,
    const float* __restrict__ dn2_b,
    const float* __restrict__ eps_p,
    float* __restrict__ out)
{
    __shared__ __align__(16) __nv_bfloat16 h_b[32 * HB];   // bf16 x tile (rows 21-31 garbage) / reused as wu_b
    __shared__ __align__(16) __nv_bfloat16 wd_b[Dv * WB];  // Wd bf16 tile
    __shared__ __align__(16) __nv_bfloat16 A_b[32 * AB];   // A*gf bf16
    __shared__ __align__(16) float hl_s[32 * 32];          // h_low (rows 21-31 junk)
    __shared__ __align__(16) float A_s[CRv];               // qn*gate (fp32)
    __shared__ __align__(16) float cv_s[Dv];
    __shared__ float mu_s[32], rs_s[32], sw_s[32], lb_s[32];
    __shared__ float gfp_s[4 * Rv];
    __shared__ __align__(16) float hid_s[Hv];
    __shared__ float sred_s[2 * Dv];
    __shared__ __align__(16) float2 gb_s[Dv];              // (gate, bu)

    const int tid = threadIdx.x;
    const int lane = tid & 31;
    const int w = tid >> 5;
    const int bp = blockIdx.x;
    const int bb = bp / Pv, pp = bp % Pv;
    const int xrow = bb * Cv * PDv + pp * Dv;

    // ---- setup ------------------------------------------------------------
    if (tid < 32) { sw_s[tid] = g_SW[tid]; lb_s[tid] = g_LB[tid]; }
    if (tid >= 21 && tid < 32) { mu_s[tid] = 0.f; rs_s[tid] = 0.f; }

    // ---- R1: load x -> h_b (bf16) + cv; stage Wd tile --------------------
    {
        float s1 = 0.f, s2 = 0.f;
        #pragma unroll
        for (int c = 0; c < Cv; c++) {
            float v = x[xrow + c * PDv + tid];
            h_b[c * HB + tid] = __float2bfloat16_rn(v);
            s1 += v; s2 += v * v;
        }
        cv_s[tid] = (s2 - s1 * s1 * (1.0f / 21.0f)) * (1.0f / 20.0f);
    }
    {
        // wd_b[256][WB]: copy 256x32 bf16 (64B rows -> 4 uint4 per row)
        char* dstb = reinterpret_cast<char*>(wd_b);
        #pragma unroll
        for (int i = 0; i < 4; i++) {
            int idx = tid + 256 * i;            // 0..1023
            int row = idx >> 2, ch = idx & 3;
            uint4 v = __ldg(reinterpret_cast<const uint4*>(g_Wdh + row * Rv + ch * 8));
            *reinterpret_cast<uint4*>(dstb + row * (WB * 2) + ch * 16) = v;
        }
    }
    __syncthreads();

    // ---- R2: LN stats (from h_b) + gate MLP1 -----------------------------
    #pragma unroll
    for (int ci = 0; ci < 3; ci++) {
        int c = w + 8 * ci;
        if (c < Cv) {
            float s = 0.f, ss = 0.f;
            #pragma unroll
            for (int k2 = 0; k2 < 4; k2++) {
                __nv_bfloat162 hv = *reinterpret_cast<const __nv_bfloat162*>(
                    &h_b[c * HB + 2 * lane + 64 * k2]);
                float2 f = __bfloat1622float2(hv);
                s += f.x + f.y; ss += f.x * f.x + f.y * f.y;
            }
            #pragma unroll
            for (int o = 16; o > 0; o >>= 1) {
                s  += __shfl_xor_sync(0xffffffffu, s, o);
                ss += __shfl_xor_sync(0xffffffffu, ss, o);
            }
            if (lane == 0) {
                float mu = s * (1.0f / 256.0f);
                float var = ss * (1.0f / 256.0f) - mu * mu;
                mu_s[c] = mu;
                rs_s[c] = rsqrtf(var + 1e-5f);
            }
        }
    }
    {
        float4 ca = *reinterpret_cast<const float4*>(&cv_s[8 * lane]);
        float4 cb = *reinterpret_cast<const float4*>(&cv_s[8 * lane + 4]);
        #pragma unroll
        for (int jj = 0; jj < 8; jj++) {
            int j = w * 8 + jj;
            uint4 wraw = __ldg(reinterpret_cast<const uint4*>(&g_dn1b[j * Dv + 8 * lane]));
            float2 f0 = __bfloat1622float2(*reinterpret_cast<__nv_bfloat162*>(&wraw.x));
            float2 f1 = __bfloat1622float2(*reinterpret_cast<__nv_bfloat162*>(&wraw.y));
            float2 f2 = __bfloat1622float2(*reinterpret_cast<__nv_bfloat162*>(&wraw.z));
            float2 f3 = __bfloat1622float2(*reinterpret_cast<__nv_bfloat162*>(&wraw.w));
            float part = ca.x * f0.x + ca.y * f0.y + ca.z * f1.x + ca.w * f1.y
                       + cb.x * f2.x + cb.y * f2.y + cb.z * f3.x + cb.w * f3.y;
            #pragma unroll
            for (int o = 16; o > 0; o >>= 1)
                part += __shfl_xor_sync(0xffffffffu, part, o);
            if (lane == 0) hid_s[j] = geluf(part + __ldg(&dn1_b[j]));
        }
    }
    __syncthreads();

    // ---- R3: ph4 MMA (h_b @ wd_b -> hl_s with LN fold) + gate MLP2 -------
    {
        const int mtile = w & 1;
        const int r0 = (w >> 1) * 8;
        const unsigned a_addr = smem_u32(h_b)
            + (unsigned)(((mtile * 16 + (lane & 15)) * HB + ((lane >> 4) << 3)) * 2);
        const unsigned b_addr = smem_u32(wd_b)
            + (unsigned)(((lane & 15) * WB + r0) * 2);
        float c0 = 0.f, c1 = 0.f, c2 = 0.f, c3 = 0.f;
        #pragma unroll
        for (int k = 0; k < 16; k++) {
            unsigned a0, a1, a2, a3, b0, b1;
            ldsm_x4(a0, a1, a2, a3, a_addr + k * 32);
            ldsm_x2t(b0, b1, b_addr + k * 16 * WB * 2);
            mma16816(c0, c1, c2, c3, a0, a1, a2, a3, b0, b1);
        }
        const int m0 = mtile * 16 + (lane >> 2);
        const int col = r0 + 2 * (lane & 3);
        float sw0 = sw_s[col], sw1 = sw_s[col + 1];
        float lb0 = lb_s[col], lb1 = lb_s[col + 1];
        float mu0 = mu_s[m0], rv0 = rs_s[m0];
        float mu1 = mu_s[m0 + 8], rv1 = rs_s[m0 + 8];
        *reinterpret_cast<float2*>(&hl_s[m0 * 32 + col]) =
            make_float2(rv0 * (c0 - mu0 * sw0) + lb0, rv0 * (c1 - mu0 * sw1) + lb1);
        *reinterpret_cast<float2*>(&hl_s[(m0 + 8) * 32 + col]) =
            make_float2(rv1 * (c2 - mu1 * sw0) + lb0, rv1 * (c3 - mu1 * sw1) + lb1);
    }
    {
        const int dp = tid & 127;
        const int jh = tid >> 7;
        float a0 = 0.f, a1 = 0.f;
        #pragma unroll 4
        for (int j4 = 0; j4 < 8; j4++) {
            int j = 32 * jh + 4 * j4;
            float4 h4 = *reinterpret_cast<const float4*>(&hid_s[j]);
            float2 w0 = __bfloat1622float2(
                __ldg(reinterpret_cast<const __nv_bfloat162*>(g_dn2b + (j + 0) * Dv) + dp));
            float2 w1 = __bfloat1622float2(
                __ldg(reinterpret_cast<const __nv_bfloat162*>(g_dn2b + (j + 1) * Dv) + dp));
            float2 w2 = __bfloat1622float2(
                __ldg(reinterpret_cast<const __nv_bfloat162*>(g_dn2b + (j + 2) * Dv) + dp));
            float2 w3 = __bfloat1622float2(
                __ldg(reinterpret_cast<const __nv_bfloat162*>(g_dn2b + (j + 3) * Dv) + dp));
            a0 = fmaf(h4.x, w0.x, fmaf(h4.y, w1.x, fmaf(h4.z, w2.x, fmaf(h4.w, w3.x, a0))));
            a1 = fmaf(h4.x, w0.y, fmaf(h4.y, w1.y, fmaf(h4.z, w2.y, fmaf(h4.w, w3.y, a1))));
        }
        sred_s[jh * Dv + 2 * dp]     = a0;
        sred_s[jh * Dv + 2 * dp + 1] = a1;
    }
    __syncthreads();

    // ---- R4: phase5 QKVG (scalar) + gate finalize + Wu tile stage --------
    {
        const int r = lane;
        const int role = w & 1;                      // 0: q&g, 1: k&v
        const int cgrp = w >> 1;                     // 0..3
        const int cstart = (cgrp == 0) ? 0 : (5 * cgrp + 1);
        const int ccnt   = (cgrp == 0) ? 6 : 5;
        const int o1 = role ? (32 + r) : r;
        const int o2 = role ? (64 + r) : (96 + r);

        float acc1[6], acc2[6];
        #pragma unroll
        for (int j = 0; j < 6; j++) { acc1[j] = 0.f; acc2[j] = 0.f; }

        #pragma unroll
        for (int pass = 0; pass < 2; pass++) {
            const int kk0 = 16 * pass;
            unsigned long long w1[8], w2[8];
            #pragma unroll
            for (int t = 0; t < 8; t++) {
                int kp = (kk0 >> 1) + t;
                w1[t] = bf2f2pk(__ldg(&g_W4b[kp * 128 + o1]));
                w2[t] = bf2f2pk(__ldg(&g_W4b[kp * 128 + o2]));
            }
            #pragma unroll
            for (int j = 0; j < 6; j++) {
                if (j < ccnt) {
                    const float* hr = hl_s + (cstart + j) * 32 + kk0;
                    unsigned long long a1p = 0ull, a2p = 0ull;
                    #pragma unroll
                    for (int q4 = 0; q4 < 4; q4++) {
                        float4 h4 = *reinterpret_cast<const float4*>(hr + 4 * q4);
                        unsigned long long hx = pk2(h4.x, h4.y), hy = pk2(h4.z, h4.w);
                        ffma2(a1p, hx, w1[2 * q4]); ffma2(a1p, hy, w1[2 * q4 + 1]);
                        ffma2(a2p, hx, w2[2 * q4]); ffma2(a2p, hy, w2[2 * q4 + 1]);
                    }
                    acc1[j] += upksum(a1p);
                    acc2[j] += upksum(a2p);
                }
            }
        }

        if (role == 0) {
            float bgr = __ldg(&bg[r]);
            #pragma unroll
            for (int j = 0; j < 6; j++) {
                if (j < ccnt) {
                    float q = acc1[j];
                    float qs = q * q;
                    #pragma unroll
                    for (int o = 16; o > 0; o >>= 1)
                        qs += __shfl_xor_sync(0xffffffffu, qs, o);
                    float qn = q / fmaxf(sqrtf(qs), 1e-12f);
                    A_s[(cstart + j) * Rv + r] = qn * sigm(acc2[j] + bgr);
                }
            }
        } else {
            float gfp = 0.f;
            #pragma unroll
            for (int j = 0; j < 6; j++) {
                if (j < ccnt) {
                    float k = acc1[j];
                    float ks = k * k;
                    #pragma unroll
                    for (int o = 16; o > 0; o >>= 1)
                        ks += __shfl_xor_sync(0xffffffffu, ks, o);
                    float kn = k / fmaxf(sqrtf(ks), 1e-12f);
                    gfp += kn * acc2[j];
                }
            }
            gfp_s[cgrp * Rv + r] = gfp;
        }
    }
    {
        float dc = sred_s[tid] + sred_s[Dv + tid];
        float ev = __ldg(eps_p);
        float gv = sigm(__ldg(&g_logits[tid]) + ev * (dc + __ldg(&dn2_b[tid])));
        gb_s[tid] = make_float2(gv, __ldg(&bu[tid]));
    }
    {
        // wu_b = Wu bf16 [32][HB] into the h_b buffer (h_b dead after ph4)
        char* dstb = reinterpret_cast<char*>(h_b);
        #pragma unroll
        for (int i = 0; i < 4; i++) {
            int idx = tid + 256 * i;             // 0..1023
            int row = idx >> 5, ch = idx & 31;   // 32 rows x 32 chunks of 16B
            uint4 v = __ldg(reinterpret_cast<const uint4*>(g_Wuh + row * Dv + ch * 8));
            *reinterpret_cast<uint4*>(dstb + row * (HB * 2) + ch * 16) = v;
        }
    }
    __syncthreads();

    // ---- R5: A_b = bf16(A * gf) ------------------------------------------
    #pragma unroll
    for (int i2 = 0; i2 < 3; i2++) {
        int idx = tid + 256 * i2;
        if (idx < CRv) {
            int r = idx & 31;
            float gf = gfp_s[r] + gfp_s[32 + r] + gfp_s[64 + r] + gfp_s[96 + r];
            A_b[(idx >> 5) * AB + r] = __float2bfloat16_rn(A_s[idx] * gf);
        }
    }
    __syncthreads();

    // ---- R6: ph6 MMA (A_b @ wu_b) + fused residual/gate epilogue ---------
    {
        const int mtile = w & 1;
        const int nb = (w >> 1) * 64;
        const unsigned a_addr = smem_u32(A_b)
            + (unsigned)(((mtile * 16 + (lane & 15)) * AB + ((lane >> 4) << 3)) * 2);
        unsigned a00, a01, a02, a03, a10, a11, a12, a13;
        ldsm_x4(a00, a01, a02, a03, a_addr);
        ldsm_x4(a10, a11, a12, a13, a_addr + 32);   // k16..31 (+16 cols * 2B)
        const unsigned b_base = smem_u32(h_b) + (unsigned)(((lane & 15) * HB) * 2);
        const int m0 = mtile * 16 + (lane >> 2);
        const int m1 = m0 + 8;
        #pragma unroll
        for (int t = 0; t < 8; t++) {
            int n0 = nb + t * 8;
            unsigned b0, b1, b2, b3;
            ldsm_x2t(b0, b1, b_base + n0 * 2);
            ldsm_x2t(b2, b3, b_base + 16 * HB * 2 + n0 * 2);
            float c0 = 0.f, c1 = 0.f, c2 = 0.f, c3 = 0.f;
            mma16816(c0, c1, c2, c3, a00, a01, a02, a03, b0, b1);
            mma16816(c0, c1, c2, c3, a10, a11, a12, a13, b2, b3);
            int d0 = n0 + 2 * (lane & 3);
            float2 g0 = gb_s[d0], g1 = gb_s[d0 + 1];
            if (m0 < Cv) {
                int gi = xrow + m0 * PDv + d0;
                float2 xv = *reinterpret_cast<const float2*>(&x[gi]);
                *reinterpret_cast<float2*>(&out[gi]) =
                    make_float2(xv.x + g0.x * (c0 + g0.y), xv.y + g1.x * (c1 + g1.y));
            }
            if (m1 < Cv) {
                int gi = xrow + m1 * PDv + d0;
                float2 xv = *reinterpret_cast<const float2*>(&x[gi]);
                *reinterpret_cast<float2*>(&out[gi]) =
                    make_float2(xv.x + g0.x * (c2 + g0.y), xv.y + g1.x * (c3 + g1.y));
            }
        }
    }
}

// ---------------------------------------------------------------------------
extern "C" void kernel_launch(void* const* d_in, const int* in_sizes, int n_in,
                              void* d_out, int out_size) {
    const float* x     = (const float*)d_in[0];
    const float* ln_w  = (const float*)d_in[1];
    const float* ln_b  = (const float*)d_in[2];
    const float* Wd    = (const float*)d_in[3];
    const float* bd    = (const float*)d_in[4];
    const float* Wq    = (const float*)d_in[5];
    const float* Wk    = (const float*)d_in[6];
    const float* Wvp   = (const float*)d_in[7];
    const float* Wg    = (const float*)d_in[8];
    const float* bg    = (const float*)d_in[9];
    const float* Wu    = (const float*)d_in[10];
    const float* bu    = (const float*)d_in[11];
    const float* cn1_w = (const float*)d_in[12];
    const float* cn1_b = (const float*)d_in[13];
    const float* cn2_w = (const float*)d_in[14];
    const float* cn2_b = (const float*)d_in[15];
    const float* dn1_w = (const float*)d_in[16];
    const float* dn1_b = (const float*)d_in[17];
    const float* dn2_w = (const float*)d_in[18];
    const float* dn2_b = (const float*)d_in[19];
    const float* eps   = (const float*)d_in[20];
    float* out = (float*)d_out;

    prep_kernel<<<202, 256>>>(ln_w, ln_b, Wd, bd, Wq, Wk, Wvp, Wg, Wu,
                              cn1_w, cn1_b, cn2_w, cn2_b, dn1_w, dn2_w);
    fused_kernel<<<BPv, 256>>>(x, bg, bu, dn1_b, dn2_b, eps, out);
}

// round 7
// speedup vs baseline: 3.0764x; 1.0600x over previous
#include <cuda_runtime.h>
#include <cuda_bf16.h>
#include <cuda_fp8.h>
#include <math.h>

#define Bv 64
#define Cv 21
#define Pv 96
#define Dv 256
#define Rv 32
#define Hv 64
#define BPv (Bv*Pv)
#define PDv (Pv*Dv)
#define CRv (Cv*Rv)

// padded smem strides (elements), all rows 16B-aligned & ldsm bank-rotated
#define HB  264   // h_b / wu_b row stride (528B = 33*16)
#define WB  40    // wd_b row stride (80B = 5*16)
#define AB  40    // A_b row stride

#define FP8S 32.0f       // fp8 weight scale
#define FP8SI (1.0f/32.0f)

// ---------------- device-global precomputed weights -------------------------
__device__ __nv_bfloat16  g_Wdh[Dv*Rv];       // [d][r] = bf16(ln_w[d]*Wd[d][r])
__device__ __nv_bfloat162 g_W4b[(Rv/2)*128];  // [(kk/2)*128+o] (phase5)
__device__ __nv_bfloat16  g_Wuh[Rv*Dv];       // [r][d] = bf16(Wu[r][d])
__device__ __nv_fp8_storage_t g_dn1f8[Hv*Dv]; // [j][d] = e4m3(32*dn1_w[d][j])
__device__ __nv_fp8_storage_t g_dn2f8[Hv*Dv]; // [j][d] = e4m3(32*dn2_w[j][d])
__device__ float g_SW[Rv];
__device__ float g_LB[Rv];
__device__ float g_logits[Dv];

static __device__ __forceinline__ float geluf(float x) {
    return 0.5f * x * (1.0f + erff(x * 0.70710678118654752f));
}
static __device__ __forceinline__ float sigm(float x) {
    return 1.0f / (1.0f + expf(-x));
}
static __device__ __forceinline__ unsigned long long pk2(float a, float b) {
    unsigned long long r;
    asm("mov.b64 %0, {%1,%2};" : "=l"(r) : "f"(a), "f"(b));
    return r;
}
static __device__ __forceinline__ void ffma2(unsigned long long& d,
                                             unsigned long long a,
                                             unsigned long long b) {
    asm("fma.rn.f32x2 %0, %1, %2, %3;" : "=l"(d) : "l"(a), "l"(b), "l"(d));
}
static __device__ __forceinline__ float upksum(unsigned long long v) {
    float lo, hi;
    asm("mov.b64 {%0,%1}, %2;" : "=f"(lo), "=f"(hi) : "l"(v));
    return lo + hi;
}
static __device__ __forceinline__ unsigned long long bf2f2pk(__nv_bfloat162 b) {
    float2 f = __bfloat1622float2(b);
    return pk2(f.x, f.y);
}
static __device__ __forceinline__ float2 fp8x2_f2(unsigned v) {
    __half2_raw hr = __nv_cvt_fp8x2_to_halfraw2((__nv_fp8x2_storage_t)(v & 0xffffu),
                                                __NV_E4M3);
    return __half22float2(*reinterpret_cast<__half2*>(&hr));
}
static __device__ __forceinline__ unsigned smem_u32(const void* p) {
    return (unsigned)__cvta_generic_to_shared(p);
}
static __device__ __forceinline__ void ldsm_x4(unsigned& r0, unsigned& r1,
                                               unsigned& r2, unsigned& r3, unsigned a) {
    asm volatile("ldmatrix.sync.aligned.m8n8.x4.shared.b16 {%0,%1,%2,%3}, [%4];"
                 : "=r"(r0), "=r"(r1), "=r"(r2), "=r"(r3) : "r"(a));
}
static __device__ __forceinline__ void ldsm_x2t(unsigned& r0, unsigned& r1, unsigned a) {
    asm volatile("ldmatrix.sync.aligned.m8n8.x2.trans.shared.b16 {%0,%1}, [%2];"
                 : "=r"(r0), "=r"(r1) : "r"(a));
}
static __device__ __forceinline__ void mma16816(float& c0, float& c1, float& c2, float& c3,
                                                unsigned a0, unsigned a1, unsigned a2, unsigned a3,
                                                unsigned b0, unsigned b1) {
    asm volatile("mma.sync.aligned.m16n8k16.row.col.f32.bf16.bf16.f32 "
                 "{%0,%1,%2,%3}, {%4,%5,%6,%7}, {%8,%9}, {%0,%1,%2,%3};"
                 : "+f"(c0), "+f"(c1), "+f"(c2), "+f"(c3)
                 : "r"(a0), "r"(a1), "r"(a2), "r"(a3), "r"(b0), "r"(b1));
}

// ---------------------------------------------------------------------------
// Prep: 202 blocks x 256 threads
// ---------------------------------------------------------------------------
__global__ void prep_kernel(const float* __restrict__ ln_w, const float* __restrict__ ln_b,
                            const float* __restrict__ Wd,   const float* __restrict__ bd,
                            const float* __restrict__ Wq,   const float* __restrict__ Wk,
                            const float* __restrict__ Wv,   const float* __restrict__ Wg,
                            const float* __restrict__ Wu,
                            const float* __restrict__ cn1_w, const float* __restrict__ cn1_b,
                            const float* __restrict__ cn2_w, const float* __restrict__ cn2_b,
                            const float* __restrict__ dn1_w, const float* __restrict__ dn2_w) {
    int bi = blockIdx.x, tid = threadIdx.x;
    if (bi < 32) {
        int idx = bi * 256 + tid;            // d*32 + r
        g_Wdh[idx] = __float2bfloat16_rn(ln_w[idx >> 5] * Wd[idx]);
    } else if (bi < 40) {
        int idx = (bi - 32) * 256 + tid;     // (kk/2)*128 + o
        int kp = idx >> 7, o = idx & 127, kk = 2 * kp;
        int m = o >> 5, r = o & 31;
        const float* src = (m == 0) ? Wq : (m == 1) ? Wk : (m == 2) ? Wv : Wg;
        g_W4b[idx] = __floats2bfloat162_rn(src[kk * Rv + r], src[(kk + 1) * Rv + r]);
    } else if (bi < 72) {
        int idx = (bi - 40) * 256 + tid;     // r*256 + d
        g_Wuh[idx] = __float2bfloat16_rn(Wu[idx]);
    } else if (bi < 136) {
        int j = bi - 72;
        g_dn1f8[j * Dv + tid] =
            __nv_cvt_float_to_fp8(dn1_w[tid * Hv + j] * FP8S, __NV_SATFINITE, __NV_E4M3);
    } else if (bi < 200) {
        int j = bi - 136;
        g_dn2f8[j * Dv + tid] =
            __nv_cvt_float_to_fp8(dn2_w[j * Dv + tid] * FP8S, __NV_SATFINITE, __NV_E4M3);
    } else if (bi == 200) {
        __shared__ float ssw[8][32], slb[8][32];
        int r = tid & 31, seg = tid >> 5;
        float sw = 0.f, lb = 0.f;
        for (int dd = 0; dd < 32; dd++) {
            int d = seg * 32 + dd;
            float wv = Wd[d * Rv + r];
            sw += ln_w[d] * wv;
            lb += ln_b[d] * wv;
        }
        ssw[seg][r] = sw; slb[seg][r] = lb;
        __syncthreads();
        if (tid < 32) {
            float a = 0.f, b2 = 0.f;
            #pragma unroll
            for (int s = 0; s < 8; s++) { a += ssw[s][tid]; b2 += slb[s][tid]; }
            g_SW[tid] = a;
            g_LB[tid] = b2 + bd[tid];
        }
    } else {
        __shared__ float hid[Hv];
        const float lc = logf(21.0f) / logf(1000.0f);
        if (tid < Hv) hid[tid] = geluf(lc * cn1_w[tid] + cn1_b[tid]);
        __syncthreads();
        float acc = cn2_b[tid];
        for (int j = 0; j < Hv; j++) acc += hid[j] * cn2_w[j * Dv + tid];
        g_logits[tid] = acc;
    }
}

// ---------------------------------------------------------------------------
// Fully-fused kernel: one CTA per (b,p). 256 thr, 8 warps, 3 CTAs/SM.
// ---------------------------------------------------------------------------
__global__ __launch_bounds__(256, 3) void fused_kernel(
    const float* __restrict__ x,
    const float* __restrict__ bg,
    const float* __restrict__ bu,
    const float* __restrict__ dn1_b,
    const float* __restrict__ dn2_b,
    const float* __restrict__ eps_p,
    float* __restrict__ out)
{
    __shared__ __align__(16) __nv_bfloat16 h_b[32 * HB];   // bf16 x tile / reused as wu_b
    __shared__ __align__(16) __nv_bfloat16 wd_b[Dv * WB];  // Wd bf16 tile
    __shared__ __align__(16) __nv_bfloat16 A_b[32 * AB];   // A*gf bf16
    __shared__ __align__(16) float hl_s[32 * 32];          // h_low (rows 21-31 junk)
    __shared__ __align__(16) float A_s[CRv];               // qn*gate (fp32)
    __shared__ __align__(16) float cv_s[Dv];
    __shared__ float mu_s[32], rs_s[32], sw_s[32], lb_s[32];
    __shared__ float gfp_s[4 * Rv];
    __shared__ __align__(16) float hid_s[Hv];
    __shared__ __align__(16) float sred_s[2 * Dv];
    __shared__ __align__(16) float2 gb_s[Dv];              // (gate, bu)

    const int tid = threadIdx.x;
    const int lane = tid & 31;
    const int w = tid >> 5;
    const int bp = blockIdx.x;
    const int bb = bp / Pv, pp = bp % Pv;
    const int xrow = bb * Cv * PDv + pp * Dv;

    if (tid < 32) { sw_s[tid] = g_SW[tid]; lb_s[tid] = g_LB[tid]; }
    if (tid >= 21 && tid < 32) { mu_s[tid] = 0.f; rs_s[tid] = 0.f; }

    // ---- R1: load x -> h_b (bf16) + cv; stage Wd tile --------------------
    {
        float s1 = 0.f, s2 = 0.f;
        #pragma unroll
        for (int c = 0; c < Cv; c++) {
            float v = x[xrow + c * PDv + tid];
            h_b[c * HB + tid] = __float2bfloat16_rn(v);
            s1 += v; s2 += v * v;
        }
        cv_s[tid] = (s2 - s1 * s1 * (1.0f / 21.0f)) * (1.0f / 20.0f);
    }
    {
        char* dstb = reinterpret_cast<char*>(wd_b);
        #pragma unroll
        for (int i = 0; i < 4; i++) {
            int idx = tid + 256 * i;            // 0..1023
            int row = idx >> 2, ch = idx & 3;
            uint4 v = __ldg(reinterpret_cast<const uint4*>(g_Wdh + row * Rv + ch * 8));
            *reinterpret_cast<uint4*>(dstb + row * (WB * 2) + ch * 16) = v;
        }
    }
    __syncthreads();

    // ---- R2: LN stats + gate MLP1 (fp8 weights) --------------------------
    #pragma unroll
    for (int ci = 0; ci < 3; ci++) {
        int c = w + 8 * ci;
        if (c < Cv) {
            float s = 0.f, ss = 0.f;
            #pragma unroll
            for (int k2 = 0; k2 < 4; k2++) {
                __nv_bfloat162 hv = *reinterpret_cast<const __nv_bfloat162*>(
                    &h_b[c * HB + 2 * lane + 64 * k2]);
                float2 f = __bfloat1622float2(hv);
                s += f.x + f.y; ss += f.x * f.x + f.y * f.y;
            }
            #pragma unroll
            for (int o = 16; o > 0; o >>= 1) {
                s  += __shfl_xor_sync(0xffffffffu, s, o);
                ss += __shfl_xor_sync(0xffffffffu, ss, o);
            }
            if (lane == 0) {
                float mu = s * (1.0f / 256.0f);
                float var = ss * (1.0f / 256.0f) - mu * mu;
                mu_s[c] = mu;
                rs_s[c] = rsqrtf(var + 1e-5f);
            }
        }
    }
    {
        float4 ca = *reinterpret_cast<const float4*>(&cv_s[8 * lane]);
        float4 cb = *reinterpret_cast<const float4*>(&cv_s[8 * lane + 4]);
        #pragma unroll
        for (int jj = 0; jj < 8; jj++) {
            int j = w * 8 + jj;
            uint2 wv = __ldg(reinterpret_cast<const uint2*>(&g_dn1f8[j * Dv + 8 * lane]));
            float2 f0 = fp8x2_f2(wv.x);
            float2 f1 = fp8x2_f2(wv.x >> 16);
            float2 f2 = fp8x2_f2(wv.y);
            float2 f3 = fp8x2_f2(wv.y >> 16);
            float part = ca.x * f0.x + ca.y * f0.y + ca.z * f1.x + ca.w * f1.y
                       + cb.x * f2.x + cb.y * f2.y + cb.z * f3.x + cb.w * f3.y;
            #pragma unroll
            for (int o = 16; o > 0; o >>= 1)
                part += __shfl_xor_sync(0xffffffffu, part, o);
            if (lane == 0) hid_s[j] = geluf(part * FP8SI + __ldg(&dn1_b[j]));
        }
    }
    __syncthreads();

    // ---- R3: warp-specialized: w<4 -> ph4 MMA; w>=4 -> gate MLP2 ---------
    if (w < 4) {
        const int mtile = w & 1;
        const int r0 = (w >> 1) * 16;
        const unsigned a_addr = smem_u32(h_b)
            + (unsigned)(((mtile * 16 + (lane & 15)) * HB + ((lane >> 4) << 3)) * 2);
        const unsigned b_addr0 = smem_u32(wd_b)
            + (unsigned)(((lane & 15) * WB + r0) * 2);
        const unsigned b_addr1 = b_addr0 + 16;     // +8 cols * 2B
        float c0[4] = {0.f, 0.f, 0.f, 0.f};
        float c1[4] = {0.f, 0.f, 0.f, 0.f};
        #pragma unroll
        for (int k = 0; k < 16; k++) {
            unsigned a0, a1, a2, a3, b0, b1;
            ldsm_x4(a0, a1, a2, a3, a_addr + k * 32);
            ldsm_x2t(b0, b1, b_addr0 + k * 16 * WB * 2);
            mma16816(c0[0], c0[1], c0[2], c0[3], a0, a1, a2, a3, b0, b1);
            ldsm_x2t(b0, b1, b_addr1 + k * 16 * WB * 2);
            mma16816(c1[0], c1[1], c1[2], c1[3], a0, a1, a2, a3, b0, b1);
        }
        const int m0 = mtile * 16 + (lane >> 2);
        const int m1 = m0 + 8;
        const float mu0 = mu_s[m0], rv0 = rs_s[m0];
        const float mu1 = mu_s[m1], rv1 = rs_s[m1];
        #pragma unroll
        for (int nt = 0; nt < 2; nt++) {
            const float* cc = nt ? c1 : c0;
            int col = r0 + nt * 8 + 2 * (lane & 3);
            float sw0 = sw_s[col], sw1 = sw_s[col + 1];
            float lb0 = lb_s[col], lb1 = lb_s[col + 1];
            *reinterpret_cast<float2*>(&hl_s[m0 * 32 + col]) =
                make_float2(rv0 * (cc[0] - mu0 * sw0) + lb0, rv0 * (cc[1] - mu0 * sw1) + lb1);
            *reinterpret_cast<float2*>(&hl_s[m1 * 32 + col]) =
                make_float2(rv1 * (cc[2] - mu1 * sw0) + lb0, rv1 * (cc[3] - mu1 * sw1) + lb1);
        }
    } else {
        // gate MLP2 on warps 4-7 (fp8 weights)
        const int local = tid - 128;          // 0..127
        const int dq = local & 63;            // d = 4*dq .. 4*dq+3
        const int jh = local >> 6;            // j-half: [32*jh, 32*jh+32)
        float a0 = 0.f, a1 = 0.f, a2 = 0.f, a3 = 0.f;
        #pragma unroll
        for (int j4 = 0; j4 < 8; j4++) {
            int j = 32 * jh + 4 * j4;
            float4 h4 = *reinterpret_cast<const float4*>(&hid_s[j]);
            #pragma unroll
            for (int t = 0; t < 4; t++) {
                unsigned wv = __ldg(reinterpret_cast<const unsigned*>(
                    &g_dn2f8[(j + t) * Dv + 4 * dq]));
                float2 w01 = fp8x2_f2(wv);
                float2 w23 = fp8x2_f2(wv >> 16);
                float hj = (t == 0) ? h4.x : (t == 1) ? h4.y : (t == 2) ? h4.z : h4.w;
                a0 = fmaf(hj, w01.x, a0); a1 = fmaf(hj, w01.y, a1);
                a2 = fmaf(hj, w23.x, a2); a3 = fmaf(hj, w23.y, a3);
            }
        }
        *reinterpret_cast<float4*>(&sred_s[jh * Dv + 4 * dq]) =
            make_float4(a0, a1, a2, a3);
    }
    __syncthreads();

    // ---- R4: phase5 QKVG (scalar, k-chunked) + gate finalize + Wu stage --
    {
        const int r = lane;
        const int role = w & 1;                      // 0: q&g, 1: k&v
        const int cgrp = w >> 1;                     // 0..3
        const int cstart = (cgrp == 0) ? 0 : (5 * cgrp + 1);
        const int ccnt   = (cgrp == 0) ? 6 : 5;
        const int o1 = role ? (32 + r) : r;
        const int o2 = role ? (64 + r) : (96 + r);

        float acc1[6], acc2[6];
        #pragma unroll
        for (int j = 0; j < 6; j++) { acc1[j] = 0.f; acc2[j] = 0.f; }

        #pragma unroll
        for (int ch = 0; ch < 4; ch++) {
            const int kk0 = 8 * ch;
            unsigned long long w1[4], w2[4];
            #pragma unroll
            for (int t = 0; t < 4; t++) {
                int kp = 4 * ch + t;
                w1[t] = bf2f2pk(__ldg(&g_W4b[kp * 128 + o1]));
                w2[t] = bf2f2pk(__ldg(&g_W4b[kp * 128 + o2]));
            }
            #pragma unroll
            for (int j = 0; j < 6; j++) {
                if (j < ccnt) {
                    const float* hr = hl_s + (cstart + j) * 32 + kk0;
                    unsigned long long a1p = 0ull, a2p = 0ull;
                    #pragma unroll
                    for (int q4 = 0; q4 < 2; q4++) {
                        float4 h4 = *reinterpret_cast<const float4*>(hr + 4 * q4);
                        unsigned long long hx = pk2(h4.x, h4.y), hy = pk2(h4.z, h4.w);
                        ffma2(a1p, hx, w1[2 * q4]); ffma2(a1p, hy, w1[2 * q4 + 1]);
                        ffma2(a2p, hx, w2[2 * q4]); ffma2(a2p, hy, w2[2 * q4 + 1]);
                    }
                    acc1[j] += upksum(a1p);
                    acc2[j] += upksum(a2p);
                }
            }
        }

        if (role == 0) {
            float bgr = __ldg(&bg[r]);
            #pragma unroll
            for (int j = 0; j < 6; j++) {
                if (j < ccnt) {
                    float q = acc1[j];
                    float qs = q * q;
                    #pragma unroll
                    for (int o = 16; o > 0; o >>= 1)
                        qs += __shfl_xor_sync(0xffffffffu, qs, o);
                    float qn = q / fmaxf(sqrtf(qs), 1e-12f);
                    A_s[(cstart + j) * Rv + r] = qn * sigm(acc2[j] + bgr);
                }
            }
        } else {
            float gfp = 0.f;
            #pragma unroll
            for (int j = 0; j < 6; j++) {
                if (j < ccnt) {
                    float k = acc1[j];
                    float ks = k * k;
                    #pragma unroll
                    for (int o = 16; o > 0; o >>= 1)
                        ks += __shfl_xor_sync(0xffffffffu, ks, o);
                    float kn = k / fmaxf(sqrtf(ks), 1e-12f);
                    gfp += kn * acc2[j];
                }
            }
            gfp_s[cgrp * Rv + r] = gfp;
        }
    }
    {
        float dc = (sred_s[tid] + sred_s[Dv + tid]) * FP8SI;
        float ev = __ldg(eps_p);
        float gv = sigm(__ldg(&g_logits[tid]) + ev * (dc + __ldg(&dn2_b[tid])));
        gb_s[tid] = make_float2(gv, __ldg(&bu[tid]));
    }
    {
        // wu_b = Wu bf16 [32][HB] into the h_b buffer (h_b dead after ph4)
        char* dstb = reinterpret_cast<char*>(h_b);
        #pragma unroll
        for (int i = 0; i < 4; i++) {
            int idx = tid + 256 * i;             // 0..1023
            int row = idx >> 5, ch = idx & 31;
            uint4 v = __ldg(reinterpret_cast<const uint4*>(g_Wuh + row * Dv + ch * 8));
            *reinterpret_cast<uint4*>(dstb + row * (HB * 2) + ch * 16) = v;
        }
    }
    __syncthreads();

    // ---- R5: A_b = bf16(A * gf) ------------------------------------------
    #pragma unroll
    for (int i2 = 0; i2 < 3; i2++) {
        int idx = tid + 256 * i2;
        if (idx < CRv) {
            int r = idx & 31;
            float gf = gfp_s[r] + gfp_s[32 + r] + gfp_s[64 + r] + gfp_s[96 + r];
            A_b[(idx >> 5) * AB + r] = __float2bfloat16_rn(A_s[idx] * gf);
        }
    }
    __syncthreads();

    // ---- R6: ph6 MMA (A_b @ wu_b) + fused residual/gate epilogue ---------
    {
        const int mtile = w & 1;
        const int nb = (w >> 1) * 64;
        const unsigned a_addr = smem_u32(A_b)
            + (unsigned)(((mtile * 16 + (lane & 15)) * AB + ((lane >> 4) << 3)) * 2);
        unsigned a00, a01, a02, a03, a10, a11, a12, a13;
        ldsm_x4(a00, a01, a02, a03, a_addr);
        ldsm_x4(a10, a11, a12, a13, a_addr + 32);
        const unsigned b_base = smem_u32(h_b) + (unsigned)(((lane & 15) * HB) * 2);
        const int m0 = mtile * 16 + (lane >> 2);
        const int m1 = m0 + 8;
        #pragma unroll
        for (int t = 0; t < 8; t++) {
            int n0 = nb + t * 8;
            unsigned b0, b1, b2, b3;
            ldsm_x2t(b0, b1, b_base + n0 * 2);
            ldsm_x2t(b2, b3, b_base + 16 * HB * 2 + n0 * 2);
            float c0 = 0.f, c1 = 0.f, c2 = 0.f, c3 = 0.f;
            mma16816(c0, c1, c2, c3, a00, a01, a02, a03, b0, b1);
            mma16816(c0, c1, c2, c3, a10, a11, a12, a13, b2, b3);
            int d0 = n0 + 2 * (lane & 3);
            float2 g0 = gb_s[d0], g1 = gb_s[d0 + 1];
            if (m0 < Cv) {
                int gi = xrow + m0 * PDv + d0;
                float2 xv = *reinterpret_cast<const float2*>(&x[gi]);
                *reinterpret_cast<float2*>(&out[gi]) =
                    make_float2(xv.x + g0.x * (c0 + g0.y), xv.y + g1.x * (c1 + g1.y));
            }
            if (m1 < Cv) {
                int gi = xrow + m1 * PDv + d0;
                float2 xv = *reinterpret_cast<const float2*>(&x[gi]);
                *reinterpret_cast<float2*>(&out[gi]) =
                    make_float2(xv.x + g0.x * (c2 + g0.y), xv.y + g1.x * (c3 + g1.y));
            }
        }
    }
}

// ---------------------------------------------------------------------------
extern "C" void kernel_launch(void* const* d_in, const int* in_sizes, int n_in,
                              void* d_out, int out_size) {
    const float* x     = (const float*)d_in[0];
    const float* ln_w  = (const float*)d_in[1];
    const float* ln_b  = (const float*)d_in[2];
    const float* Wd    = (const float*)d_in[3];
    const float* bd    = (const float*)d_in[4];
    const float* Wq    = (const float*)d_in[5];
    const float* Wk    = (const float*)d_in[6];
    const float* Wvp   = (const float*)d_in[7];
    const float* Wg    = (const float*)d_in[8];
    const float* bg    = (const float*)d_in[9];
    const float* Wu    = (const float*)d_in[10];
    const float* bu    = (const float*)d_in[11];
    const float* cn1_w = (const float*)d_in[12];
    const float* cn1_b = (const float*)d_in[13];
    const float* cn2_w = (const float*)d_in[14];
    const float* cn2_b = (const float*)d_in[15];
    const float* dn1_w = (const float*)d_in[16];
    const float* dn1_b = (const float*)d_in[17];
    const float* dn2_w = (const float*)d_in[18];
    const float* dn2_b = (const float*)d_in[19];
    const float* eps   = (const float*)d_in[20];
    float* out = (float*)d_out;

    prep_kernel<<<202, 256>>>(ln_w, ln_b, Wd, bd, Wq, Wk, Wvp, Wg, Wu,
                              cn1_w, cn1_b, cn2_w, cn2_b, dn1_w, dn2_w);
    fused_kernel<<<BPv, 256>>>(x, bg, bu, dn1_b, dn2_b, eps, out);
}

// round 8
// speedup vs baseline: 4.1038x; 1.3339x over previous
#include <cuda_runtime.h>
#include <cuda_bf16.h>
#include <cuda_fp8.h>
#include <math.h>

#define Bv 64
#define Cv 21
#define Pv 96
#define Dv 256
#define Rv 32
#define Hv 64
#define BPv (Bv*Pv)
#define PDv (Pv*Dv)

// padded smem strides (elements); all 16B multiples with odd-16B rotation
#define HB  264   // h_b / wu_b row stride (528B)
#define WB  40    // wd_b row stride (80B)
#define AB  40    // A_b / hl_b row stride (80B)
#define W4B 136   // w4_b row stride (272B)
#define MB  264   // mixed row stride

#define FP8S 32.0f
#define FP8SI (1.0f/32.0f)

// ---------------- device-global precomputed weights -------------------------
__device__ __align__(16) __nv_bfloat16 g_Wdh[Dv*Rv];        // [d][r] = bf16(ln_w*Wd)
__device__ __align__(16) __nv_bfloat16 g_W4h[Rv*128];       // [kk][o] plain bf16
__device__ __align__(16) __nv_bfloat16 g_Wuh[Rv*Dv];        // [r][d]
__device__ __align__(16) __nv_fp8_storage_t g_dn1f8[Hv*Dv]; // [j][d]
__device__ __align__(16) __nv_fp8_storage_t g_dn2f8[Hv*Dv]; // [j][d]
__device__ float g_SW[Rv];
__device__ float g_LB[Rv];
__device__ float g_logits[Dv];

static __device__ __forceinline__ float geluf(float x) {
    return 0.5f * x * (1.0f + erff(x * 0.70710678118654752f));
}
static __device__ __forceinline__ float sigm(float x) {
    return 1.0f / (1.0f + expf(-x));
}
static __device__ __forceinline__ float2 fp8x2_f2(unsigned v) {
    __half2_raw hr = __nv_cvt_fp8x2_to_halfraw2((__nv_fp8x2_storage_t)(v & 0xffffu),
                                                __NV_E4M3);
    return __half22float2(*reinterpret_cast<__half2*>(&hr));
}
static __device__ __forceinline__ unsigned smem_u32(const void* p) {
    return (unsigned)__cvta_generic_to_shared(p);
}
static __device__ __forceinline__ void ldsm_x4(unsigned& r0, unsigned& r1,
                                               unsigned& r2, unsigned& r3, unsigned a) {
    asm volatile("ldmatrix.sync.aligned.m8n8.x4.shared.b16 {%0,%1,%2,%3}, [%4];"
                 : "=r"(r0), "=r"(r1), "=r"(r2), "=r"(r3) : "r"(a));
}
static __device__ __forceinline__ void ldsm_x2t(unsigned& r0, unsigned& r1, unsigned a) {
    asm volatile("ldmatrix.sync.aligned.m8n8.x2.trans.shared.b16 {%0,%1}, [%2];"
                 : "=r"(r0), "=r"(r1) : "r"(a));
}
static __device__ __forceinline__ void mma16816(float& c0, float& c1, float& c2, float& c3,
                                                unsigned a0, unsigned a1, unsigned a2, unsigned a3,
                                                unsigned b0, unsigned b1) {
    asm volatile("mma.sync.aligned.m16n8k16.row.col.f32.bf16.bf16.f32 "
                 "{%0,%1,%2,%3}, {%4,%5,%6,%7}, {%8,%9}, {%0,%1,%2,%3};"
                 : "+f"(c0), "+f"(c1), "+f"(c2), "+f"(c3)
                 : "r"(a0), "r"(a1), "r"(a2), "r"(a3), "r"(b0), "r"(b1));
}
static __device__ __forceinline__ void cp_async16(unsigned dst, const void* src) {
    asm volatile("cp.async.ca.shared.global [%0], [%1], 16;" :: "r"(dst), "l"(src));
}
static __device__ __forceinline__ void cp_commit() {
    asm volatile("cp.async.commit_group;");
}
static __device__ __forceinline__ void cp_wait0() {
    asm volatile("cp.async.wait_group 0;");
}
static __device__ __forceinline__ unsigned hmul2bf(unsigned a, unsigned b) {
    __nv_bfloat162 r = __hmul2(*reinterpret_cast<__nv_bfloat162*>(&a),
                               *reinterpret_cast<__nv_bfloat162*>(&b));
    return *reinterpret_cast<unsigned*>(&r);
}
static __device__ __forceinline__ __nv_bfloat162 f2bf2(float a, float b) {
    return __floats2bfloat162_rn(a, b);
}

// ---------------------------------------------------------------------------
// Prep: 210 blocks x 256 threads
// ---------------------------------------------------------------------------
__global__ void prep_kernel(const float* __restrict__ ln_w, const float* __restrict__ ln_b,
                            const float* __restrict__ Wd,   const float* __restrict__ bd,
                            const float* __restrict__ Wq,   const float* __restrict__ Wk,
                            const float* __restrict__ Wv,   const float* __restrict__ Wg,
                            const float* __restrict__ Wu,
                            const float* __restrict__ cn1_w, const float* __restrict__ cn1_b,
                            const float* __restrict__ cn2_w, const float* __restrict__ cn2_b,
                            const float* __restrict__ dn1_w, const float* __restrict__ dn2_w) {
    int bi = blockIdx.x, tid = threadIdx.x;
    if (bi < 32) {
        int idx = bi * 256 + tid;            // d*32 + r
        g_Wdh[idx] = __float2bfloat16_rn(ln_w[idx >> 5] * Wd[idx]);
    } else if (bi < 48) {
        int idx = (bi - 32) * 256 + tid;     // kk*128 + o
        int kk = idx >> 7, o = idx & 127, m = o >> 5, r = o & 31;
        const float* src = (m == 0) ? Wq : (m == 1) ? Wk : (m == 2) ? Wv : Wg;
        g_W4h[idx] = __float2bfloat16_rn(src[kk * Rv + r]);
    } else if (bi < 80) {
        int idx = (bi - 48) * 256 + tid;     // r*256 + d
        g_Wuh[idx] = __float2bfloat16_rn(Wu[idx]);
    } else if (bi < 144) {
        int j = bi - 80;
        g_dn1f8[j * Dv + tid] =
            __nv_cvt_float_to_fp8(dn1_w[tid * Hv + j] * FP8S, __NV_SATFINITE, __NV_E4M3);
    } else if (bi < 208) {
        int j = bi - 144;
        g_dn2f8[j * Dv + tid] =
            __nv_cvt_float_to_fp8(dn2_w[j * Dv + tid] * FP8S, __NV_SATFINITE, __NV_E4M3);
    } else if (bi == 208) {
        __shared__ float ssw[8][32], slb[8][32];
        int r = tid & 31, seg = tid >> 5;
        float sw = 0.f, lb = 0.f;
        for (int dd = 0; dd < 32; dd++) {
            int d = seg * 32 + dd;
            float wv = Wd[d * Rv + r];
            sw += ln_w[d] * wv;
            lb += ln_b[d] * wv;
        }
        ssw[seg][r] = sw; slb[seg][r] = lb;
        __syncthreads();
        if (tid < 32) {
            float a = 0.f, b2 = 0.f;
            #pragma unroll
            for (int s = 0; s < 8; s++) { a += ssw[s][tid]; b2 += slb[s][tid]; }
            g_SW[tid] = a;
            g_LB[tid] = b2 + bd[tid];
        }
    } else {
        __shared__ float hid[Hv];
        const float lc = logf(21.0f) / logf(1000.0f);
        if (tid < Hv) hid[tid] = geluf(lc * cn1_w[tid] + cn1_b[tid]);
        __syncthreads();
        float acc = cn2_b[tid];
        for (int j = 0; j < Hv; j++) acc += hid[j] * cn2_w[j * Dv + tid];
        g_logits[tid] = acc;
    }
}

// ---------------------------------------------------------------------------
// Fully-fused kernel: one CTA per (b,p). 256 thr, 8 warps, 3 CTAs/SM.
// ---------------------------------------------------------------------------
__global__ __launch_bounds__(256, 3) void fused_kernel(
    const float* __restrict__ x,
    const float* __restrict__ bg,
    const float* __restrict__ bu,
    const float* __restrict__ dn1_b,
    const float* __restrict__ dn2_b,
    const float* __restrict__ eps_p,
    float* __restrict__ out)
{
    __shared__ __align__(16) __nv_bfloat16 h_b[32 * HB];    // x tile, later wu_b
    __shared__ __align__(16) __nv_bfloat16 wd_b[Dv * WB];   // Wd tile, later mixed
    __shared__ __align__(16) __nv_bfloat16 w4_b[Rv * W4B];  // W4 tile
    __shared__ __align__(16) __nv_bfloat16 A_b[32 * AB];    // qn*sig(g) (unscaled)
    __shared__ __align__(16) __nv_bfloat16 hl_b[32 * AB];   // h_low bf16 (junk rows 0)
    __shared__ __align__(16) float cv_s[Dv];
    __shared__ float mu_s[32], rs_s[32];
    __shared__ __align__(16) float sw_s[32], lb_s[32];
    __shared__ __align__(16) float bg_s[32];
    __shared__ __align__(16) float gfp_s[2 * Rv];
    __shared__ __align__(8)  __nv_bfloat16 gf_b[32];
    __shared__ __align__(16) float hid_s[Hv];
    __shared__ __align__(16) float sred_s[2 * Dv];
    __shared__ __align__(16) float2 gb_s[Dv];               // (gate, bu)

    __nv_bfloat16* mixed_b = wd_b;   // wd_b dead after ph4; reuse for mixed

    const int tid = threadIdx.x;
    const int lane = tid & 31;
    const int w = tid >> 5;
    const int bp = blockIdx.x;
    const int bb = bp / Pv, pp = bp % Pv;
    const int xrow = bb * Cv * PDv + pp * Dv;

    if (tid < 32) {
        sw_s[tid] = g_SW[tid];
        lb_s[tid] = g_LB[tid];
        bg_s[tid] = __ldg(&bg[tid]);
    }
    if (tid >= 21 && tid < 32) { mu_s[tid] = 0.f; rs_s[tid] = 0.f; }

    // ---- R1: x -> h_b + cv; cp.async stage Wd + W4 -----------------------
    {
        float s1 = 0.f, s2 = 0.f;
        #pragma unroll
        for (int c = 0; c < Cv; c++) {
            float v = x[xrow + c * PDv + tid];
            h_b[c * HB + tid] = __float2bfloat16_rn(v);
            s1 += v; s2 += v * v;
        }
        cv_s[tid] = (s2 - s1 * s1 * (1.0f / 21.0f)) * (1.0f / 20.0f);
    }
    {
        unsigned wdbase = smem_u32(wd_b);
        #pragma unroll
        for (int i = 0; i < 4; i++) {
            int idx = tid + 256 * i;            // 1024 chunks of 16B
            int row = idx >> 2, ch = idx & 3;
            cp_async16(wdbase + (unsigned)((row * WB + ch * 8) * 2),
                       g_Wdh + row * Rv + ch * 8);
        }
        unsigned w4base = smem_u32(w4_b);
        #pragma unroll
        for (int i = 0; i < 2; i++) {
            int idx = tid + 256 * i;            // 512 chunks
            int row = idx >> 4, ch = idx & 15;
            cp_async16(w4base + (unsigned)((row * W4B + ch * 8) * 2),
                       g_W4h + row * 128 + ch * 8);
        }
        cp_commit();
    }
    __syncthreads();

    // ---- R2: LN stats + gate MLP1 (fp8) ----------------------------------
    #pragma unroll
    for (int ci = 0; ci < 3; ci++) {
        int c = w + 8 * ci;
        if (c < Cv) {
            float s = 0.f, ss = 0.f;
            #pragma unroll
            for (int k2 = 0; k2 < 4; k2++) {
                __nv_bfloat162 hv = *reinterpret_cast<const __nv_bfloat162*>(
                    &h_b[c * HB + 2 * lane + 64 * k2]);
                float2 f = __bfloat1622float2(hv);
                s += f.x + f.y; ss += f.x * f.x + f.y * f.y;
            }
            #pragma unroll
            for (int o = 16; o > 0; o >>= 1) {
                s  += __shfl_xor_sync(0xffffffffu, s, o);
                ss += __shfl_xor_sync(0xffffffffu, ss, o);
            }
            if (lane == 0) {
                float mu = s * (1.0f / 256.0f);
                float var = ss * (1.0f / 256.0f) - mu * mu;
                mu_s[c] = mu;
                rs_s[c] = rsqrtf(var + 1e-5f);
            }
        }
    }
    {
        float4 ca = *reinterpret_cast<const float4*>(&cv_s[8 * lane]);
        float4 cb = *reinterpret_cast<const float4*>(&cv_s[8 * lane + 4]);
        #pragma unroll
        for (int jj = 0; jj < 8; jj++) {
            int j = w * 8 + jj;
            uint2 wv = __ldg(reinterpret_cast<const uint2*>(&g_dn1f8[j * Dv + 8 * lane]));
            float2 f0 = fp8x2_f2(wv.x);
            float2 f1 = fp8x2_f2(wv.x >> 16);
            float2 f2 = fp8x2_f2(wv.y);
            float2 f3 = fp8x2_f2(wv.y >> 16);
            float part = ca.x * f0.x + ca.y * f0.y + ca.z * f1.x + ca.w * f1.y
                       + cb.x * f2.x + cb.y * f2.y + cb.z * f3.x + cb.w * f3.y;
            #pragma unroll
            for (int o = 16; o > 0; o >>= 1)
                part += __shfl_xor_sync(0xffffffffu, part, o);
            if (lane == 0) hid_s[j] = geluf(part * FP8SI + __ldg(&dn1_b[j]));
        }
    }
    cp_wait0();
    __syncthreads();

    // ---- R3: warps 0-3 ph4 MMA -> hl_b; warps 4-7 gate MLP2 --------------
    if (w < 4) {
        const int mtile = w & 1;
        const int r0 = (w >> 1) * 16;
        const unsigned a_addr = smem_u32(h_b)
            + (unsigned)(((mtile * 16 + (lane & 15)) * HB + ((lane >> 4) << 3)) * 2);
        const unsigned b_addr0 = smem_u32(wd_b)
            + (unsigned)(((lane & 15) * WB + r0) * 2);
        const unsigned b_addr1 = b_addr0 + 16;
        float c0[4] = {0.f, 0.f, 0.f, 0.f};
        float c1[4] = {0.f, 0.f, 0.f, 0.f};
        #pragma unroll
        for (int k = 0; k < 16; k++) {
            unsigned a0, a1, a2, a3, b0, b1;
            ldsm_x4(a0, a1, a2, a3, a_addr + k * 32);
            ldsm_x2t(b0, b1, b_addr0 + k * 16 * WB * 2);
            mma16816(c0[0], c0[1], c0[2], c0[3], a0, a1, a2, a3, b0, b1);
            ldsm_x2t(b0, b1, b_addr1 + k * 16 * WB * 2);
            mma16816(c1[0], c1[1], c1[2], c1[3], a0, a1, a2, a3, b0, b1);
        }
        const int m0 = mtile * 16 + (lane >> 2);
        const int m1 = m0 + 8;
        const bool v0 = m0 < Cv, v1 = m1 < Cv;
        const float mu0 = mu_s[m0], rv0 = rs_s[m0];
        const float mu1 = mu_s[m1], rv1 = rs_s[m1];
        #pragma unroll
        for (int nt = 0; nt < 2; nt++) {
            const float* cc = nt ? c1 : c0;
            int col = r0 + nt * 8 + 2 * (lane & 3);
            float sw0 = sw_s[col], sw1 = sw_s[col + 1];
            float lb0 = lb_s[col], lb1 = lb_s[col + 1];
            float h00 = v0 ? (rv0 * (cc[0] - mu0 * sw0) + lb0) : 0.f;
            float h01 = v0 ? (rv0 * (cc[1] - mu0 * sw1) + lb1) : 0.f;
            float h10 = v1 ? (rv1 * (cc[2] - mu1 * sw0) + lb0) : 0.f;
            float h11 = v1 ? (rv1 * (cc[3] - mu1 * sw1) + lb1) : 0.f;
            *reinterpret_cast<__nv_bfloat162*>(&hl_b[m0 * AB + col]) = f2bf2(h00, h01);
            *reinterpret_cast<__nv_bfloat162*>(&hl_b[m1 * AB + col]) = f2bf2(h10, h11);
        }
    } else {
        const int local = tid - 128;
        const int dq = local & 63;
        const int jh = local >> 6;
        float a0 = 0.f, a1 = 0.f, a2 = 0.f, a3 = 0.f;
        #pragma unroll
        for (int j4 = 0; j4 < 8; j4++) {
            int j = 32 * jh + 4 * j4;
            float4 h4 = *reinterpret_cast<const float4*>(&hid_s[j]);
            #pragma unroll
            for (int t = 0; t < 4; t++) {
                unsigned wv = __ldg(reinterpret_cast<const unsigned*>(
                    &g_dn2f8[(j + t) * Dv + 4 * dq]));
                float2 w01 = fp8x2_f2(wv);
                float2 w23 = fp8x2_f2(wv >> 16);
                float hj = (t == 0) ? h4.x : (t == 1) ? h4.y : (t == 2) ? h4.z : h4.w;
                a0 = fmaf(hj, w01.x, a0); a1 = fmaf(hj, w01.y, a1);
                a2 = fmaf(hj, w23.x, a2); a3 = fmaf(hj, w23.y, a3);
            }
        }
        *reinterpret_cast<float4*>(&sred_s[jh * Dv + 4 * dq]) =
            make_float4(a0, a1, a2, a3);
    }
    __syncthreads();

    // ---- R4: warps 0-3 ph5 MMA (QKVG); warps 4-7 gate finalize + Wu stage -
    if (w < 4) {
        const int role = w & 1;      // 0: q&g, 1: k&v
        const int mt = w >> 1;
        const unsigned a_addr = smem_u32(hl_b)
            + (unsigned)(((mt * 16 + (lane & 15)) * AB + ((lane >> 4) << 3)) * 2);
        unsigned a0, a1, a2, a3, a4, a5, a6, a7;
        ldsm_x4(a0, a1, a2, a3, a_addr);
        ldsm_x4(a4, a5, a6, a7, a_addr + 32);
        const int ob1 = role ? 32 : 0;    // k : q
        const int ob2 = role ? 64 : 96;   // v : g
        const unsigned bbase = smem_u32(w4_b) + (unsigned)(((lane & 15) * W4B) * 2);
        const unsigned bk16 = 16 * W4B * 2;
        float c1v[16], c2v[16];
        #pragma unroll
        for (int i = 0; i < 16; i++) { c1v[i] = 0.f; c2v[i] = 0.f; }
        #pragma unroll
        for (int nb = 0; nb < 4; nb++) {
            unsigned b0, b1;
            ldsm_x2t(b0, b1, bbase + (ob1 + nb * 8) * 2);
            mma16816(c1v[4*nb], c1v[4*nb+1], c1v[4*nb+2], c1v[4*nb+3],
                     a0, a1, a2, a3, b0, b1);
            ldsm_x2t(b0, b1, bbase + bk16 + (ob1 + nb * 8) * 2);
            mma16816(c1v[4*nb], c1v[4*nb+1], c1v[4*nb+2], c1v[4*nb+3],
                     a4, a5, a6, a7, b0, b1);
            ldsm_x2t(b0, b1, bbase + (ob2 + nb * 8) * 2);
            mma16816(c2v[4*nb], c2v[4*nb+1], c2v[4*nb+2], c2v[4*nb+3],
                     a0, a1, a2, a3, b0, b1);
            ldsm_x2t(b0, b1, bbase + bk16 + (ob2 + nb * 8) * 2);
            mma16816(c2v[4*nb], c2v[4*nb+1], c2v[4*nb+2], c2v[4*nb+3],
                     a4, a5, a6, a7, b0, b1);
        }
        // row norms of c1 (q or k): rows m0 = mt*16 + lane>>2, m1 = m0+8
        float qs0 = 0.f, qs1 = 0.f;
        #pragma unroll
        for (int nb = 0; nb < 4; nb++) {
            qs0 += c1v[4*nb] * c1v[4*nb] + c1v[4*nb+1] * c1v[4*nb+1];
            qs1 += c1v[4*nb+2] * c1v[4*nb+2] + c1v[4*nb+3] * c1v[4*nb+3];
        }
        qs0 += __shfl_xor_sync(0xffffffffu, qs0, 1);
        qs0 += __shfl_xor_sync(0xffffffffu, qs0, 2);
        qs1 += __shfl_xor_sync(0xffffffffu, qs1, 1);
        qs1 += __shfl_xor_sync(0xffffffffu, qs1, 2);
        float rn0 = 1.f / fmaxf(sqrtf(qs0), 1e-12f);
        float rn1 = 1.f / fmaxf(sqrtf(qs1), 1e-12f);
        if (role == 0) {
            const int m0 = mt * 16 + (lane >> 2);
            const int m1 = m0 + 8;
            #pragma unroll
            for (int nb = 0; nb < 4; nb++) {
                int rcol = nb * 8 + 2 * (lane & 3);
                float2 bgv = *reinterpret_cast<const float2*>(&bg_s[rcol]);
                float A0 = c1v[4*nb]   * rn0 * sigm(c2v[4*nb]   + bgv.x);
                float A1 = c1v[4*nb+1] * rn0 * sigm(c2v[4*nb+1] + bgv.y);
                float A2 = c1v[4*nb+2] * rn1 * sigm(c2v[4*nb+2] + bgv.x);
                float A3 = c1v[4*nb+3] * rn1 * sigm(c2v[4*nb+3] + bgv.y);
                *reinterpret_cast<__nv_bfloat162*>(&A_b[m0 * AB + rcol]) = f2bf2(A0, A1);
                *reinterpret_cast<__nv_bfloat162*>(&A_b[m1 * AB + rcol]) = f2bf2(A2, A3);
            }
        } else {
            #pragma unroll
            for (int nb = 0; nb < 4; nb++) {
                float g0 = c1v[4*nb]   * rn0 * c2v[4*nb]   + c1v[4*nb+2] * rn1 * c2v[4*nb+2];
                float g1 = c1v[4*nb+1] * rn0 * c2v[4*nb+1] + c1v[4*nb+3] * rn1 * c2v[4*nb+3];
                g0 += __shfl_xor_sync(0xffffffffu, g0, 4);
                g0 += __shfl_xor_sync(0xffffffffu, g0, 8);
                g0 += __shfl_xor_sync(0xffffffffu, g0, 16);
                g1 += __shfl_xor_sync(0xffffffffu, g1, 4);
                g1 += __shfl_xor_sync(0xffffffffu, g1, 8);
                g1 += __shfl_xor_sync(0xffffffffu, g1, 16);
                if (lane < 4) {
                    gfp_s[mt * 32 + nb * 8 + 2 * lane]     = g0;
                    gfp_s[mt * 32 + nb * 8 + 2 * lane + 1] = g1;
                }
            }
        }
    } else {
        // gate finalize: 2 d per thread
        const int local = tid - 128;
        const float ev = __ldg(eps_p);
        #pragma unroll
        for (int t = 0; t < 2; t++) {
            int dd = 2 * local + t;
            float dc = (sred_s[dd] + sred_s[Dv + dd]) * FP8SI;
            float gv = sigm(__ldg(&g_logits[dd]) + ev * (dc + __ldg(&dn2_b[dd])));
            gb_s[dd] = make_float2(gv, __ldg(&bu[dd]));
        }
        // cp.async stage Wu into h_b (dead after ph4)
        unsigned wubase = smem_u32(h_b);
        #pragma unroll
        for (int i = 0; i < 8; i++) {
            int idx = local + 128 * i;           // 1024 chunks
            int row = idx >> 5, ch = idx & 31;
            cp_async16(wubase + (unsigned)((row * HB + ch * 8) * 2),
                       g_Wuh + row * Dv + ch * 8);
        }
        cp_commit();
    }
    __syncthreads();

    // ---- R5: gf finalize + wait Wu ---------------------------------------
    if (tid < 32)
        gf_b[tid] = __float2bfloat16_rn(gfp_s[tid] + gfp_s[32 + tid]);
    cp_wait0();
    __syncthreads();

    // ---- R6: ph6 MMA ((A*gf) @ wu_b) -> mixed_b --------------------------
    {
        const int mtile = w & 1;
        const int nb0 = (w >> 1) * 64;
        const unsigned a_addr = smem_u32(A_b)
            + (unsigned)(((mtile * 16 + (lane & 15)) * AB + ((lane >> 4) << 3)) * 2);
        unsigned a00, a01, a02, a03, a10, a11, a12, a13;
        ldsm_x4(a00, a01, a02, a03, a_addr);
        ldsm_x4(a10, a11, a12, a13, a_addr + 32);
        // scale A-frags by gf (k-indexed)
        {
            const __nv_bfloat162* gf2 = reinterpret_cast<const __nv_bfloat162*>(gf_b);
            int kc = lane & 3;
            unsigned s0 = *reinterpret_cast<const unsigned*>(&gf2[kc]);
            unsigned s1 = *reinterpret_cast<const unsigned*>(&gf2[kc + 4]);
            unsigned s2 = *reinterpret_cast<const unsigned*>(&gf2[kc + 8]);
            unsigned s3 = *reinterpret_cast<const unsigned*>(&gf2[kc + 12]);
            a00 = hmul2bf(a00, s0); a01 = hmul2bf(a01, s0);
            a02 = hmul2bf(a02, s1); a03 = hmul2bf(a03, s1);
            a10 = hmul2bf(a10, s2); a11 = hmul2bf(a11, s2);
            a12 = hmul2bf(a12, s3); a13 = hmul2bf(a13, s3);
        }
        const unsigned b_base = smem_u32(h_b) + (unsigned)(((lane & 15) * HB) * 2);
        const int m0 = mtile * 16 + (lane >> 2);
        const int m1 = m0 + 8;
        #pragma unroll
        for (int t = 0; t < 8; t++) {
            int n0 = nb0 + t * 8;
            unsigned b0, b1, b2, b3;
            ldsm_x2t(b0, b1, b_base + n0 * 2);
            ldsm_x2t(b2, b3, b_base + 16 * HB * 2 + n0 * 2);
            float c0 = 0.f, c1 = 0.f, c2 = 0.f, c3 = 0.f;
            mma16816(c0, c1, c2, c3, a00, a01, a02, a03, b0, b1);
            mma16816(c0, c1, c2, c3, a10, a11, a12, a13, b2, b3);
            int d0 = n0 + 2 * (lane & 3);
            if (m0 < Cv)
                *reinterpret_cast<__nv_bfloat162*>(&mixed_b[m0 * MB + d0]) = f2bf2(c0, c1);
            if (m1 < Cv)
                *reinterpret_cast<__nv_bfloat162*>(&mixed_b[m1 * MB + d0]) = f2bf2(c2, c3);
        }
    }
    __syncthreads();

    // ---- R7: coalesced out = x + gate*(mixed + bu) -----------------------
    {
        float2 gbv = gb_s[tid];
        #pragma unroll
        for (int c = 0; c < Cv; c++) {
            float mx = __bfloat162float(mixed_b[c * MB + tid]);
            int gi = xrow + c * PDv + tid;
            out[gi] = x[gi] + gbv.x * (mx + gbv.y);
        }
    }
}

// ---------------------------------------------------------------------------
extern "C" void kernel_launch(void* const* d_in, const int* in_sizes, int n_in,
                              void* d_out, int out_size) {
    const float* x     = (const float*)d_in[0];
    const float* ln_w  = (const float*)d_in[1];
    const float* ln_b  = (const float*)d_in[2];
    const float* Wd    = (const float*)d_in[3];
    const float* bd    = (const float*)d_in[4];
    const float* Wq    = (const float*)d_in[5];
    const float* Wk    = (const float*)d_in[6];
    const float* Wvp   = (const float*)d_in[7];
    const float* Wg    = (const float*)d_in[8];
    const float* bg    = (const float*)d_in[9];
    const float* Wu    = (const float*)d_in[10];
    const float* bu    = (const float*)d_in[11];
    const float* cn1_w = (const float*)d_in[12];
    const float* cn1_b = (const float*)d_in[13];
    const float* cn2_w = (const float*)d_in[14];
    const float* cn2_b = (const float*)d_in[15];
    const float* dn1_w = (const float*)d_in[16];
    const float* dn1_b = (const float*)d_in[17];
    const float* dn2_w = (const float*)d_in[18];
    const float* dn2_b = (const float*)d_in[19];
    const float* eps   = (const float*)d_in[20];
    float* out = (float*)d_out;

    prep_kernel<<<210, 256>>>(ln_w, ln_b, Wd, bd, Wq, Wk, Wvp, Wg, Wu,
                              cn1_w, cn1_b, cn2_w, cn2_b, dn1_w, dn2_w);
    fused_kernel<<<BPv, 256>>>(x, bg, bu, dn1_b, dn2_b, eps, out);
}